// round 9
// baseline (speedup 1.0000x reference)
#include <cuda_runtime.h>
#include <cuda_bf16.h>
#include <math.h>
#include <stdint.h>

// ---------------- problem constants ----------------
#define B   2
#define S   2048
#define D   2048
#define HQ  16
#define HKV 8
#define HD  128
#define FF  8192
#define KCAP 256
#define BSROWS (B*S)          // 4096
#define RMAX 512
#define EPSF 1e-6f

// ---------------- device scratch ----------------
__device__ float d_rw[BSROWS];
__device__ float d_thresh[B];
__device__ int   d_selidx[BSROWS];
__device__ int   d_selcnt[B];
__device__ int   d_off[B+1];
__device__ int   d_rows[1];
__device__ int   d_row_b[RMAX];
__device__ int   d_row_p[RMAX];
__device__ int   d_selg[BSROWS];
__device__ float d_x   [(size_t)RMAX*D];
__device__ float d_q   [(size_t)RMAX*HQ*HD];
__device__ float d_k   [(size_t)RMAX*HKV*HD];
__device__ float d_v   [(size_t)RMAX*HKV*HD];
__device__ float d_gg  [(size_t)RMAX*FF];
__device__ float d_uu  [(size_t)RMAX*FF];
__device__ float d_part[(size_t)4*RMAX*D];

// compact split-bf16 [hi|lo] (2K per row) weights and activations
#define OFF_WQ 0
#define OFF_WK (OFF_WQ + (size_t)2048*2*D)
#define OFF_WV (OFF_WK + (size_t)1024*2*D)
#define OFF_WO (OFF_WV + (size_t)1024*2*D)
#define OFF_WG (OFF_WO + (size_t)2048*2*D)
#define OFF_WU (OFF_WG + (size_t)8192*2*D)
#define OFF_WD (OFF_WU + (size_t)8192*2*D)
#define W2_TOTAL (OFF_WD + (size_t)2048*2*FF)
__device__ __nv_bfloat16 d_w2[W2_TOTAL];
__device__ __nv_bfloat16 d_a2[(size_t)RMAX*2*FF];

// ---------------- helpers ----------------
__device__ __forceinline__ uint32_t smem_to_u32(const void* p) {
    uint32_t a;
    asm("{ .reg .u64 t; cvta.to.shared.u64 t, %1; cvt.u32.u64 %0, t; }" : "=r"(a) : "l"(p));
    return a;
}
__device__ __forceinline__ void cp_async16(uint32_t dst, const void* src, int sz) {
    asm volatile("cp.async.cg.shared.global [%0], [%1], 16, %2;"
                 :: "r"(dst), "l"(src), "r"(sz) : "memory");
}
__device__ __forceinline__ void cp_commit() { asm volatile("cp.async.commit_group;" ::: "memory"); }
__device__ __forceinline__ void cp_wait2()  { asm volatile("cp.async.wait_group 2;" ::: "memory"); }
__device__ __forceinline__ void ldsm4(uint32_t& r0, uint32_t& r1, uint32_t& r2, uint32_t& r3, uint32_t a) {
    asm volatile("ldmatrix.sync.aligned.m8n8.x4.shared.b16 {%0,%1,%2,%3}, [%4];"
                 : "=r"(r0), "=r"(r1), "=r"(r2), "=r"(r3) : "r"(a));
}
__device__ __forceinline__ void mma_bf16(float* c, const uint32_t* a, uint32_t b0, uint32_t b1) {
    asm volatile("mma.sync.aligned.m16n8k16.row.col.f32.bf16.bf16.f32 "
                 "{%0,%1,%2,%3}, {%4,%5,%6,%7}, {%8,%9}, {%0,%1,%2,%3};"
                 : "+f"(c[0]), "+f"(c[1]), "+f"(c[2]), "+f"(c[3])
                 : "r"(a[0]), "r"(a[1]), "r"(a[2]), "r"(a[3]), "r"(b0), "r"(b1));
}
__device__ __forceinline__ uint32_t pack_bf2(float a, float b) {
    __nv_bfloat162 t = __floats2bfloat162_rn(a, b);
    return *(uint32_t*)&t;
}
__device__ __forceinline__ void split4(float4 v, uint2& hi, uint2& lo) {
    float h0 = __bfloat162float(__float2bfloat16(v.x));
    float h1 = __bfloat162float(__float2bfloat16(v.y));
    float h2 = __bfloat162float(__float2bfloat16(v.z));
    float h3 = __bfloat162float(__float2bfloat16(v.w));
    hi = make_uint2(pack_bf2(h0,h1), pack_bf2(h2,h3));
    lo = make_uint2(pack_bf2(v.x-h0, v.y-h1), pack_bf2(v.z-h2, v.w-h3));
}

// ---------------- merged weight conversion (7 segments, shifts not divides) ----------------
struct WSeg { const float* src; __nv_bfloat16* dst; int total; int kshift; int K; };
struct WAll { WSeg s[7]; };

__global__ void convert_all_kernel(WAll wa) {
    #pragma unroll 1
    for (int sgi = 0; sgi < 7; sgi++) {
        const float* __restrict__ src = wa.s[sgi].src;
        __nv_bfloat16* __restrict__ dst = wa.s[sgi].dst;
        int K = wa.s[sgi].K;
        int ks = wa.s[sgi].kshift;          // log2(K/8)
        int total = wa.s[sgi].total;        // N * K/8
        int kmask = (1 << ks) - 1;
        for (int idx = blockIdx.x * 256 + threadIdx.x; idx < total; idx += gridDim.x * 256) {
            int n = idx >> ks, c8 = (idx & kmask) << 3;
            const float* sp = src + (size_t)n * K + c8;
            float4 v0 = *(const float4*)(sp);
            float4 v1 = *(const float4*)(sp + 4);
            uint2 hiA, loA, hiB, loB;
            split4(v0, hiA, loA);
            split4(v1, hiB, loB);
            size_t b = (size_t)n * 2 * K + c8;
            *(uint4*)(dst + b)     = make_uint4(hiA.x, hiA.y, hiB.x, hiB.y);
            *(uint4*)(dst + b + K) = make_uint4(loA.x, loA.y, loB.x, loB.y);
        }
    }
}

// ---------------- tensor-core GEMM (bf16 split-3 via virtual K remap) ----------------
// Virtual K3 = 3K: vA(k)=k<2K?k:k-2K over A2=[hi|lo]; vW(k)=k<K?k:k-K over W2=[hi|lo].
// CTA tile 128x128, 256 threads (2x4 warps, 64x32 warp tile), BK=64,
// 4-stage cp.async pipeline + register double-buffered ldmatrix slices.
struct Seg { const __nv_bfloat16* W2; const float* bias; float* C; int N; int ntiles; };
struct GArgs { const __nv_bfloat16* A2; int K; int kSplit; int nseg; Seg s[3]; };

#define STAGES 4
#define STAGE_BYTES 32768   // A 16KB + W 16KB (128 rows x 128 bytes)
#define SM_TOTAL (STAGES*STAGE_BYTES)   // 131072

__global__ void __launch_bounds__(256) mma_gemm(GArgs ga) {
    extern __shared__ char smem[];
    uint32_t sb = smem_to_u32(smem);
    int tid = threadIdx.x;
    int rows = d_rows[0]; if (rows > RMAX) rows = RMAX;
    int m0 = blockIdx.y * 128;
    int Kp = ga.K;
    int K3 = 3 * Kp;

    Seg sg = ga.s[0];
    int nt = blockIdx.x;
    if (ga.nseg > 1 && nt >= ga.s[0].ntiles) {
        nt -= ga.s[0].ntiles; sg = ga.s[1];
        if (ga.nseg > 2 && nt >= ga.s[1].ntiles) { nt -= ga.s[1].ntiles; sg = ga.s[2]; }
    }
    int n0g = nt * 128;
    int kLen = K3 / ga.kSplit;
    int kOff = blockIdx.z * kLen;
    int iters = kLen / 64;

    const __nv_bfloat16* Abase = ga.A2;
    const __nv_bfloat16* Wbase = sg.W2 + (size_t)n0g * 2 * Kp;

    int lrow[4], lch[4]; uint32_t lsw[4];
    #pragma unroll
    for (int q = 0; q < 4; q++) {
        int j = tid + q * 256;
        lrow[q] = j >> 3; lch[q] = j & 7;
        lsw[q] = lrow[q] * 128 + ((lch[q] ^ (lrow[q] & 7)) << 4);
    }

    #define LOAD_STAGE(stage, kElem) do { \
        int _aK = (kElem) < 2*Kp ? (kElem) : (kElem) - 2*Kp; \
        int _wK = (kElem) < Kp   ? (kElem) : (kElem) - Kp; \
        uint32_t sA = sb + (stage) * STAGE_BYTES; \
        uint32_t sW = sA + 16384; \
        _Pragma("unroll") \
        for (int q = 0; q < 4; q++) { \
            int gm = m0 + lrow[q]; \
            cp_async16(sA + lsw[q], Abase + (size_t)gm * 2 * Kp + _aK + lch[q]*8, gm < rows ? 16 : 0); \
            cp_async16(sW + lsw[q], Wbase + (size_t)lrow[q] * 2 * Kp + _wK + lch[q]*8, 16); \
        } \
    } while (0)

    LOAD_STAGE(0, kOff); cp_commit();
    if (iters > 1) LOAD_STAGE(1, kOff + 64); cp_commit();
    if (iters > 2) LOAD_STAGE(2, kOff + 128); cp_commit();

    int lane = tid & 31, wid = tid >> 5;
    int wm = wid >> 2, wn = wid & 3;
    float acc[4][4][4];
    #pragma unroll
    for (int a = 0; a < 4; a++)
        #pragma unroll
        for (int b = 0; b < 4; b++)
            #pragma unroll
            for (int c = 0; c < 4; c++) acc[a][b][c] = 0.f;

    int arow_[4];
    #pragma unroll
    for (int mi = 0; mi < 4; mi++) arow_[mi] = wm * 64 + mi * 16 + (lane & 15);
    int ach_ = lane >> 4;
    int brow_[2];
    #pragma unroll
    for (int p = 0; p < 2; p++) brow_[p] = wn * 32 + p * 16 + (lane & 7) + ((lane >> 4) << 3);
    int bch_ = (lane >> 3) & 1;

    // register slice double buffer
    uint32_t af[2][4][4], b0[2][4], b1[2][4];

    #define LOAD_SLICE(buf, sA, sW, s2) do { \
        _Pragma("unroll") \
        for (int mi = 0; mi < 4; mi++) { \
            int row = arow_[mi]; \
            int ch = 2 * (s2) + ach_; \
            uint32_t ad = (sA) + row * 128 + ((ch ^ (row & 7)) << 4); \
            ldsm4(af[buf][mi][0], af[buf][mi][1], af[buf][mi][2], af[buf][mi][3], ad); \
        } \
        _Pragma("unroll") \
        for (int p = 0; p < 2; p++) { \
            int row = brow_[p]; \
            int ch = 2 * (s2) + bch_; \
            uint32_t bd = (sW) + row * 128 + ((ch ^ (row & 7)) << 4); \
            uint32_t r0, r1, r2, r3; \
            ldsm4(r0, r1, r2, r3, bd); \
            b0[buf][2*p] = r0; b1[buf][2*p] = r1; b0[buf][2*p+1] = r2; b1[buf][2*p+1] = r3; \
        } \
    } while (0)

    for (int i = 0; i < iters; i++) {
        cp_wait2();
        __syncthreads();
        int nf = i + STAGES - 1;
        if (nf < iters) LOAD_STAGE(nf & 3, kOff + nf * 64);
        cp_commit();

        uint32_t sA = sb + (i & 3) * STAGE_BYTES;
        uint32_t sW = sA + 16384;
        LOAD_SLICE(0, sA, sW, 0);
        #pragma unroll
        for (int s2 = 0; s2 < 4; s2++) {
            int cur = s2 & 1;
            if (s2 < 3) LOAD_SLICE(cur ^ 1, sA, sW, s2 + 1);
            #pragma unroll
            for (int mi = 0; mi < 4; mi++)
                #pragma unroll
                for (int ni = 0; ni < 4; ni++)
                    mma_bf16(acc[mi][ni], af[cur][mi], b0[cur][ni], b1[cur][ni]);
        }
        __syncthreads();
    }

    float* Cp = sg.C + (ga.kSplit > 1 ? (size_t)blockIdx.z * RMAX * sg.N : 0);
    int rr = lane >> 2;
    int cc = (lane & 3) * 2;
    #pragma unroll
    for (int mi = 0; mi < 4; mi++) {
        int m1 = m0 + wm * 64 + mi * 16 + rr;
        #pragma unroll
        for (int ni = 0; ni < 4; ni++) {
            int n1 = n0g + wn * 32 + ni * 8 + cc;
            float bx = 0.f, by = 0.f;
            if (sg.bias) { bx = sg.bias[n1]; by = sg.bias[n1 + 1]; }
            if (m1 < rows)
                *(float2*)(Cp + (size_t)m1 * sg.N + n1) =
                    make_float2(acc[mi][ni][0] + bx, acc[mi][ni][1] + by);
            if (m1 + 8 < rows)
                *(float2*)(Cp + (size_t)(m1 + 8) * sg.N + n1) =
                    make_float2(acc[mi][ni][2] + bx, acc[mi][ni][3] + by);
        }
    }
    #undef LOAD_STAGE
    #undef LOAD_SLICE
}

// ---------------- router / topk / select+map ----------------
__global__ void router_kernel(const float* __restrict__ hs, const float* __restrict__ rwv) {
    int row  = blockIdx.x * 8 + (threadIdx.x >> 5);
    int lane = threadIdx.x & 31;
    if (row >= BSROWS) return;
    const float* x = hs + (size_t)row * D;
    float s = 0.f;
    for (int i = lane; i < D; i += 32) s += x[i] * rwv[i];
    #pragma unroll
    for (int o = 16; o; o >>= 1) s += __shfl_xor_sync(0xffffffffu, s, o);
    if (lane == 0) d_rw[row] = s;
}

__global__ void topk_kernel() {
    __shared__ float s[S];
    int b = blockIdx.x;
    int t = threadIdx.x;
    s[t] = d_rw[b*S + t]; s[t + 1024] = d_rw[b*S + t + 1024];
    for (int k = 2; k <= S; k <<= 1)
        for (int j = k >> 1; j > 0; j >>= 1) {
            __syncthreads();
            for (int i = t; i < S; i += 1024) {
                int ixj = i ^ j;
                if (ixj > i) {
                    bool up = ((i & k) == 0);
                    float a = s[i], c = s[ixj];
                    if ((a > c) == up) { s[i] = c; s[ixj] = a; }
                }
            }
        }
    __syncthreads();
    if (t == 0) d_thresh[b] = s[S - KCAP];
}

__global__ void selmap_kernel() {
    int t = threadIdx.x;                      // 1024 threads
    for (int i = t; i < BSROWS; i += 1024) d_selg[i] = -1;
    int wid = t >> 5, lane = t & 31;
    if (wid < B) {
        int b = wid;
        float th = d_thresh[b];
        int total = 0;
        for (int c = 0; c < S/32; c++) {
            int idx = c*32 + lane;
            bool f = d_rw[b*S + idx] >= th;
            unsigned m = __ballot_sync(0xffffffffu, f);
            int pre = __popc(m & ((1u << lane) - 1u));
            if (f) d_selidx[b*S + total + pre] = idx;
            total += __popc(m);
        }
        if (lane == 0) d_selcnt[b] = total;
    }
    __syncthreads();
    int c0 = d_selcnt[0], c1 = d_selcnt[1];
    int rows = c0 + c1; if (rows > RMAX) rows = RMAX;
    if (t == 0) { d_off[0]=0; d_off[1]=c0; d_off[2]=c0+c1; d_rows[0]=rows; }
    for (int i = t; i < c0; i += 1024) if (i < RMAX) {
        int p = d_selidx[i];
        d_row_b[i] = 0; d_row_p[i] = p; d_selg[p] = i;
    }
    for (int i = t; i < c1; i += 1024) if (c0 + i < RMAX) {
        int p = d_selidx[S + i];
        d_row_b[c0+i] = 1; d_row_p[c0+i] = p; d_selg[S + p] = c0 + i;
    }
}

// ---------------- gather + rmsnorm -> a2 (and d_x) fused ----------------
__global__ void gather_rms_a2_kernel(const float* __restrict__ hs, const float* __restrict__ w) {
    int g = blockIdx.x;
    if (g >= d_rows[0]) return;
    int b = d_row_b[g], p = d_row_p[g];
    const float4* src = (const float4*)(hs + ((size_t)b*S + p) * D);
    float4* dx = (float4*)(d_x + (size_t)g * D);
    float ss = 0.f;
    for (int i = threadIdx.x; i < D/4; i += 256) {
        float4 v = src[i]; dx[i] = v;
        ss += v.x*v.x + v.y*v.y + v.z*v.z + v.w*v.w;
    }
    __shared__ float red[8];
    int lane = threadIdx.x & 31, wid = threadIdx.x >> 5;
    #pragma unroll
    for (int o = 16; o; o >>= 1) ss += __shfl_xor_sync(0xffffffffu, ss, o);
    if (lane == 0) red[wid] = ss;
    __syncthreads();
    if (threadIdx.x == 0) { float v=0.f; for (int i=0;i<8;i++) v+=red[i]; red[0]=v; }
    __syncthreads();
    float inv = rsqrtf(red[0] / (float)D + EPSF);
    __nv_bfloat16* drow = d_a2 + (size_t)g * 2 * D;
    const float4* wv4 = (const float4*)w;
    for (int i = threadIdx.x; i < D/4; i += 256) {
        float4 v = dx[i], ww = wv4[i];
        float4 hv = make_float4(v.x*inv*ww.x, v.y*inv*ww.y, v.z*inv*ww.z, v.w*inv*ww.w);
        uint2 hi, lo; split4(hv, hi, lo);
        *(uint2*)(drow + i*4)     = hi;
        *(uint2*)(drow + D + i*4) = lo;
    }
}

// ---------------- O-reduce(2) + residual + rmsnorm -> a2, updates d_x ----------------
__global__ void rms_reduce_a2_kernel(const float* __restrict__ w) {
    int g = blockIdx.x;
    if (g >= d_rows[0]) return;
    float4* dx = (float4*)(d_x + (size_t)g * D);
    const float4* p0 = (const float4*)(d_part + (size_t)g * D);
    const float4* p1 = (const float4*)(d_part + (size_t)RMAX * D + (size_t)g * D);
    float ss = 0.f;
    for (int i = threadIdx.x; i < D/4; i += 256) {
        float4 v = dx[i], a = p0[i], b = p1[i];
        v.x += a.x + b.x; v.y += a.y + b.y; v.z += a.z + b.z; v.w += a.w + b.w;
        dx[i] = v;
        ss += v.x*v.x + v.y*v.y + v.z*v.z + v.w*v.w;
    }
    __shared__ float red[8];
    int lane = threadIdx.x & 31, wid = threadIdx.x >> 5;
    #pragma unroll
    for (int o = 16; o; o >>= 1) ss += __shfl_xor_sync(0xffffffffu, ss, o);
    if (lane == 0) red[wid] = ss;
    __syncthreads();
    if (threadIdx.x == 0) { float v=0.f; for (int i=0;i<8;i++) v+=red[i]; red[0]=v; }
    __syncthreads();
    float inv = rsqrtf(red[0] / (float)D + EPSF);
    __nv_bfloat16* drow = d_a2 + (size_t)g * 2 * D;
    const float4* wv4 = (const float4*)w;
    for (int i = threadIdx.x; i < D/4; i += 256) {
        float4 v = dx[i], ww = wv4[i];
        float4 hv = make_float4(v.x*inv*ww.x, v.y*inv*ww.y, v.z*inv*ww.z, v.w*inv*ww.w);
        uint2 hi, lo; split4(hv, hi, lo);
        *(uint2*)(drow + i*4)     = hi;
        *(uint2*)(drow + D + i*4) = lo;
    }
}

// ---------------- RoPE ----------------
__global__ void rope_kernel() {
    int g = blockIdx.x;
    if (g >= d_rows[0]) return;
    float fp = (float)d_row_p[g];
    const float L2_10000 = 13.287712379549449f;
    for (int idx = threadIdx.x; idx < (HQ + HKV) * 64; idx += 256) {
        int head = idx >> 6;
        int i = idx & 63;
        float inv = exp2f(-(float)i * (L2_10000 / 64.0f));
        float fr = fp * inv;
        float c = cosf(fr), s = sinf(fr);
        float* ptr;
        if (head < HQ) ptr = d_q + (size_t)g*(HQ*HD) + head*HD;
        else           ptr = d_k + (size_t)g*(HKV*HD) + (head-HQ)*HD;
        float x1 = ptr[i], x2 = ptr[i+64];
        ptr[i]    = x1*c - x2*s;
        ptr[i+64] = x2*c + x1*s;
    }
}

// ---------------- attention -> a2 directly ----------------
__global__ void attn_kernel() {
    int g = blockIdx.x;
    if (g >= d_rows[0]) return;
    int h = threadIdx.y + blockIdx.y * 8;
    int b = d_row_b[g];
    int off = d_off[b];
    int r = g - off;
    int p = d_row_p[g];
    int lane = threadIdx.x;
    int kvh = h >> 1;

    float4 qv = *(const float4*)(d_q + (size_t)g*(HQ*HD) + h*HD + lane*4);
    const float scale = 0.08838834764831843f;

    float m = -INFINITY, l = 0.f;
    float4 acc = make_float4(0.f, 0.f, 0.f, 0.f);

    for (int j = 0; j <= r; j++) {
        const float* kp = d_k + (size_t)(off + j)*(HKV*HD) + kvh*HD;
        float4 kv = *(const float4*)(kp + lane*4);
        float sdot = qv.x*kv.x + qv.y*kv.y + qv.z*kv.z + qv.w*kv.w;
        #pragma unroll
        for (int o = 16; o; o >>= 1) sdot += __shfl_xor_sync(0xffffffffu, sdot, o);
        float sc = sdot * scale;
        float mn = fmaxf(m, sc);
        float eo = expf(m - mn);
        float ec = expf(sc - mn);
        const float* vp = d_v + (size_t)(off + j)*(HKV*HD) + kvh*HD;
        float4 vv = *(const float4*)(vp + lane*4);
        l = l*eo + ec;
        acc.x = acc.x*eo + ec*vv.x;
        acc.y = acc.y*eo + ec*vv.y;
        acc.z = acc.z*eo + ec*vv.z;
        acc.w = acc.w*eo + ec*vv.w;
        m = mn;
    }
    int zc = p - r;
    if (zc > 0) {
        float mn = fmaxf(m, 0.f);
        float eo = expf(m - mn);
        l = l*eo + (float)zc * expf(-mn);
        acc.x *= eo; acc.y *= eo; acc.z *= eo; acc.w *= eo;
    }
    float invl = 1.f / l;
    float4 o4 = make_float4(acc.x*invl, acc.y*invl, acc.z*invl, acc.w*invl);
    uint2 hi, lo; split4(o4, hi, lo);
    __nv_bfloat16* drow = d_a2 + (size_t)g * 2 * D + h * HD + lane * 4;
    *(uint2*)(drow)     = hi;
    *(uint2*)(drow + D) = lo;
}

// ---------------- silu(g)*u -> a2 (K=FF) ----------------
__global__ void silu_a2_kernel() {
    int g = blockIdx.x;
    if (g >= d_rows[0]) return;
    const float4* gr = (const float4*)(d_gg + (size_t)g * FF);
    const float4* ur = (const float4*)(d_uu + (size_t)g * FF);
    __nv_bfloat16* drow = d_a2 + (size_t)g * 2 * FF;
    for (int i = threadIdx.x; i < FF/4; i += 256) {
        float4 x = gr[i], u = ur[i];
        float4 s;
        s.x = (x.x / (1.f + expf(-x.x))) * u.x;
        s.y = (x.y / (1.f + expf(-x.y))) * u.y;
        s.z = (x.z / (1.f + expf(-x.z))) * u.z;
        s.w = (x.w / (1.f + expf(-x.w))) * u.w;
        uint2 hi, lo; split4(s, hi, lo);
        *(uint2*)(drow + i*4)      = hi;
        *(uint2*)(drow + FF + i*4) = lo;
    }
}

// ---------------- fused output: passthrough OR (residual + down-reduce(4)) * rw ----------------
__global__ void out_kernel(const float* __restrict__ hs, float* __restrict__ out) {
    int r = blockIdx.x;
    int g = d_selg[r];
    const float4* src = (const float4*)(hs + (size_t)r * D);
    float4* dst = (float4*)(out + (size_t)r * D);
    if (g < 0) {
        for (int i = threadIdx.x; i < D/4; i += 256) dst[i] = src[i];
    } else {
        float sc = d_rw[r];
        const float4* xs = (const float4*)(d_x + (size_t)g * D);
        const float4* p0 = (const float4*)(d_part + (size_t)g * D);
        const float4* p1 = (const float4*)(d_part + (size_t)RMAX * D + (size_t)g * D);
        const float4* p2 = (const float4*)(d_part + (size_t)2 * RMAX * D + (size_t)g * D);
        const float4* p3 = (const float4*)(d_part + (size_t)3 * RMAX * D + (size_t)g * D);
        for (int i = threadIdx.x; i < D/4; i += 256) {
            float4 v = xs[i], a = p0[i], b = p1[i], c = p2[i], d = p3[i];
            v.x = (v.x + a.x + b.x + c.x + d.x) * sc;
            v.y = (v.y + a.y + b.y + c.y + d.y) * sc;
            v.z = (v.z + a.z + b.z + c.z + d.z) * sc;
            v.w = (v.w + a.w + b.w + c.w + d.w) * sc;
            dst[i] = v;
        }
    }
}

// ---------------- launch ----------------
extern "C" void kernel_launch(void* const* d_in, const int* in_sizes, int n_in,
                              void* d_out, int out_size) {
    const float* hs    = (const float*)d_in[0];
    const float* rwv   = (const float*)d_in[1];
    const float* wq    = (const float*)d_in[2];
    const float* bq    = (const float*)d_in[3];
    const float* wk    = (const float*)d_in[4];
    const float* bk    = (const float*)d_in[5];
    const float* wv    = (const float*)d_in[6];
    const float* bv    = (const float*)d_in[7];
    const float* wo    = (const float*)d_in[8];
    const float* wgate = (const float*)d_in[9];
    const float* wup   = (const float*)d_in[10];
    const float* wdown = (const float*)d_in[11];
    const float* ln1w  = (const float*)d_in[12];
    const float* ln2w  = (const float*)d_in[13];
    float* out = (float*)d_out;

    float *px, *pq, *pk, *pv, *pg, *pu, *ppart;
    __nv_bfloat16 *pw2, *pa2;
    cudaGetSymbolAddress((void**)&px,    d_x);
    cudaGetSymbolAddress((void**)&pq,    d_q);
    cudaGetSymbolAddress((void**)&pk,    d_k);
    cudaGetSymbolAddress((void**)&pv,    d_v);
    cudaGetSymbolAddress((void**)&pg,    d_gg);
    cudaGetSymbolAddress((void**)&pu,    d_uu);
    cudaGetSymbolAddress((void**)&pw2,   d_w2);
    cudaGetSymbolAddress((void**)&pa2,   d_a2);
    cudaGetSymbolAddress((void**)&ppart, d_part);

    static int attr_done = 0;
    if (!attr_done) {
        cudaFuncSetAttribute(mma_gemm, cudaFuncAttributeMaxDynamicSharedMemorySize, SM_TOTAL);
        attr_done = 1;
    }

    router_kernel<<<BSROWS/8, 256>>>(hs, rwv);
    topk_kernel<<<B, 1024>>>();
    selmap_kernel<<<1, 1024>>>();
    gather_rms_a2_kernel<<<RMAX, 256>>>(hs, ln1w);

    // all weight conversions in one launch (shift-indexed)
    {
        WAll wa;
        wa.s[0] = { wq,    pw2 + OFF_WQ, 2048*(D/8),  8,  D };
        wa.s[1] = { wk,    pw2 + OFF_WK, 1024*(D/8),  8,  D };
        wa.s[2] = { wv,    pw2 + OFF_WV, 1024*(D/8),  8,  D };
        wa.s[3] = { wo,    pw2 + OFF_WO, 2048*(D/8),  8,  D };
        wa.s[4] = { wgate, pw2 + OFF_WG, 8192*(D/8),  8,  D };
        wa.s[5] = { wup,   pw2 + OFF_WU, 8192*(D/8),  8,  D };
        wa.s[6] = { wdown, pw2 + OFF_WD, 2048*(FF/8), 10, FF };
        convert_all_kernel<<<2368, 256>>>(wa);
    }

    // QKV GEMM
    {
        GArgs ga = {};
        ga.A2 = pa2; ga.K = D; ga.kSplit = 1; ga.nseg = 3;
        ga.s[0] = { pw2 + OFF_WQ, bq, pq, HQ*HD,  16 };
        ga.s[1] = { pw2 + OFF_WK, bk, pk, HKV*HD, 8  };
        ga.s[2] = { pw2 + OFF_WV, bv, pv, HKV*HD, 8  };
        mma_gemm<<<dim3(32, 4, 1), 256, SM_TOTAL>>>(ga);
    }
    rope_kernel<<<RMAX, 256>>>();
    attn_kernel<<<dim3(RMAX, HQ/8), dim3(32, 8)>>>();
    // O projection, split-K 2 -> partials
    {
        GArgs ga = {};
        ga.A2 = pa2; ga.K = D; ga.kSplit = 2; ga.nseg = 1;
        ga.s[0] = { pw2 + OFF_WO, nullptr, ppart, D, 16 };
        mma_gemm<<<dim3(16, 4, 2), 256, SM_TOTAL>>>(ga);
    }
    // fused: reduce(2) + residual + rmsnorm2 -> a2 (updates d_x)
    rms_reduce_a2_kernel<<<RMAX, 256>>>(ln2w);
    // gate + up merged
    {
        GArgs ga = {};
        ga.A2 = pa2; ga.K = D; ga.kSplit = 1; ga.nseg = 2;
        ga.s[0] = { pw2 + OFF_WG, nullptr, pg, FF, 64 };
        ga.s[1] = { pw2 + OFF_WU, nullptr, pu, FF, 64 };
        mma_gemm<<<dim3(128, 4, 1), 256, SM_TOTAL>>>(ga);
    }
    silu_a2_kernel<<<RMAX, 256>>>();
    // down, split-K 4 -> partials (reduced in out_kernel)
    {
        GArgs ga = {};
        ga.A2 = pa2; ga.K = FF; ga.kSplit = 4; ga.nseg = 1;
        ga.s[0] = { pw2 + OFF_WD, nullptr, ppart, D, 16 };
        mma_gemm<<<dim3(16, 4, 4), 256, SM_TOTAL>>>(ga);
    }

    // fused output: passthrough or (d_x + Σ parts) * rw
    out_kernel<<<BSROWS, 256>>>(hs, out);
}

// round 10
// speedup vs baseline: 1.0976x; 1.0976x over previous
#include <cuda_runtime.h>
#include <cuda_bf16.h>
#include <math.h>
#include <stdint.h>

// ---------------- problem constants ----------------
#define B   2
#define S   2048
#define D   2048
#define HQ  16
#define HKV 8
#define HD  128
#define FF  8192
#define KCAP 256
#define BSROWS (B*S)          // 4096
#define RMAX 512
#define EPSF 1e-6f

// ---------------- device scratch ----------------
__device__ float d_rw[BSROWS];
__device__ float d_thresh[B];
__device__ int   d_selidx[BSROWS];
__device__ int   d_selcnt[B];
__device__ int   d_off[B+1];
__device__ int   d_rows[1];
__device__ int   d_row_b[RMAX];
__device__ int   d_row_p[RMAX];
__device__ int   d_selg[BSROWS];
__device__ float d_x   [(size_t)RMAX*D];
__device__ float d_q   [(size_t)RMAX*HQ*HD];
__device__ float d_k   [(size_t)RMAX*HKV*HD];
__device__ float d_v   [(size_t)RMAX*HKV*HD];
__device__ float d_gg  [(size_t)RMAX*FF];
__device__ float d_uu  [(size_t)RMAX*FF];
__device__ float d_part[(size_t)4*RMAX*D];

// compact split-bf16 [hi|lo] (2K per row) weights and activations
#define OFF_WQ 0
#define OFF_WK (OFF_WQ + (size_t)2048*2*D)
#define OFF_WV (OFF_WK + (size_t)1024*2*D)
#define OFF_WO (OFF_WV + (size_t)1024*2*D)
#define OFF_WG (OFF_WO + (size_t)2048*2*D)
#define OFF_WU (OFF_WG + (size_t)8192*2*D)
#define OFF_WD (OFF_WU + (size_t)8192*2*D)
#define W2_TOTAL (OFF_WD + (size_t)2048*2*FF)
__device__ __nv_bfloat16 d_w2[W2_TOTAL];
__device__ __nv_bfloat16 d_a2[(size_t)RMAX*2*FF];

// ---------------- helpers ----------------
__device__ __forceinline__ uint32_t smem_to_u32(const void* p) {
    uint32_t a;
    asm("{ .reg .u64 t; cvta.to.shared.u64 t, %1; cvt.u32.u64 %0, t; }" : "=r"(a) : "l"(p));
    return a;
}
__device__ __forceinline__ void cp_async16(uint32_t dst, const void* src, int sz) {
    asm volatile("cp.async.cg.shared.global [%0], [%1], 16, %2;"
                 :: "r"(dst), "l"(src), "r"(sz) : "memory");
}
__device__ __forceinline__ void cp_commit() { asm volatile("cp.async.commit_group;" ::: "memory"); }
__device__ __forceinline__ void cp_wait1()  { asm volatile("cp.async.wait_group 1;" ::: "memory"); }
__device__ __forceinline__ void ldsm4(uint32_t& r0, uint32_t& r1, uint32_t& r2, uint32_t& r3, uint32_t a) {
    asm volatile("ldmatrix.sync.aligned.m8n8.x4.shared.b16 {%0,%1,%2,%3}, [%4];"
                 : "=r"(r0), "=r"(r1), "=r"(r2), "=r"(r3) : "r"(a));
}
__device__ __forceinline__ void mma_bf16(float* c, const uint32_t* a, uint32_t b0, uint32_t b1) {
    asm volatile("mma.sync.aligned.m16n8k16.row.col.f32.bf16.bf16.f32 "
                 "{%0,%1,%2,%3}, {%4,%5,%6,%7}, {%8,%9}, {%0,%1,%2,%3};"
                 : "+f"(c[0]), "+f"(c[1]), "+f"(c[2]), "+f"(c[3])
                 : "r"(a[0]), "r"(a[1]), "r"(a[2]), "r"(a[3]), "r"(b0), "r"(b1));
}
__device__ __forceinline__ uint32_t pack_bf2(float a, float b) {
    __nv_bfloat162 t = __floats2bfloat162_rn(a, b);
    return *(uint32_t*)&t;
}
__device__ __forceinline__ void split4(float4 v, uint2& hi, uint2& lo) {
    float h0 = __bfloat162float(__float2bfloat16(v.x));
    float h1 = __bfloat162float(__float2bfloat16(v.y));
    float h2 = __bfloat162float(__float2bfloat16(v.z));
    float h3 = __bfloat162float(__float2bfloat16(v.w));
    hi = make_uint2(pack_bf2(h0,h1), pack_bf2(h2,h3));
    lo = make_uint2(pack_bf2(v.x-h0, v.y-h1), pack_bf2(v.z-h2, v.w-h3));
}

// ---------------- merged weight conversion (7 segments) ----------------
struct WSeg { const float* src; __nv_bfloat16* dst; int total; int kshift; int K; };
struct WAll { WSeg s[7]; };

__global__ void convert_all_kernel(WAll wa) {
    #pragma unroll 1
    for (int sgi = 0; sgi < 7; sgi++) {
        const float* __restrict__ src = wa.s[sgi].src;
        __nv_bfloat16* __restrict__ dst = wa.s[sgi].dst;
        int K = wa.s[sgi].K;
        int ks = wa.s[sgi].kshift;
        int total = wa.s[sgi].total;
        int kmask = (1 << ks) - 1;
        for (int idx = blockIdx.x * 256 + threadIdx.x; idx < total; idx += gridDim.x * 256) {
            int n = idx >> ks, c8 = (idx & kmask) << 3;
            const float* sp = src + (size_t)n * K + c8;
            float4 v0 = *(const float4*)(sp);
            float4 v1 = *(const float4*)(sp + 4);
            uint2 hiA, loA, hiB, loB;
            split4(v0, hiA, loA);
            split4(v1, hiB, loB);
            size_t b = (size_t)n * 2 * K + c8;
            *(uint4*)(dst + b)     = make_uint4(hiA.x, hiA.y, hiB.x, hiB.y);
            *(uint4*)(dst + b + K) = make_uint4(loA.x, loA.y, loB.x, loB.y);
        }
    }
}

// ---------------- tensor-core GEMM (round-7 proven config) ----------------
// Virtual K3 = 3K: vA(k)=k<2K?k:k-2K over A2=[hi|lo]; vW(k)=k<K?k:k-K over W2=[hi|lo].
// CTA tile 128x128, 256 threads (2x4 warps, 64x32 warp tile), BK=64, 3-stage cp.async.
struct Seg { const __nv_bfloat16* W2; const float* bias; float* C; int N; int ntiles; };
struct GArgs { const __nv_bfloat16* A2; int K; int kSplit; int nseg; Seg s[3]; };

#define STAGES 3
#define STAGE_BYTES 32768   // A 16KB + W 16KB (128 rows x 128 bytes each)
#define SM_TOTAL (STAGES*STAGE_BYTES)

__global__ void __launch_bounds__(256) mma_gemm(GArgs ga) {
    extern __shared__ char smem[];
    uint32_t sb = smem_to_u32(smem);
    int tid = threadIdx.x;
    int rows = d_rows[0]; if (rows > RMAX) rows = RMAX;
    int m0 = blockIdx.y * 128;
    int Kp = ga.K;
    int K3 = 3 * Kp;

    Seg sg = ga.s[0];
    int nt = blockIdx.x;
    if (ga.nseg > 1 && nt >= ga.s[0].ntiles) {
        nt -= ga.s[0].ntiles; sg = ga.s[1];
        if (ga.nseg > 2 && nt >= ga.s[1].ntiles) { nt -= ga.s[1].ntiles; sg = ga.s[2]; }
    }
    int n0g = nt * 128;
    int kLen = K3 / ga.kSplit;
    int kOff = blockIdx.z * kLen;
    int iters = kLen / 64;

    const __nv_bfloat16* Abase = ga.A2;
    const __nv_bfloat16* Wbase = sg.W2 + (size_t)n0g * 2 * Kp;

    int lrow[4], lch[4]; uint32_t lsw[4];
    #pragma unroll
    for (int q = 0; q < 4; q++) {
        int j = tid + q * 256;
        lrow[q] = j >> 3; lch[q] = j & 7;
        lsw[q] = lrow[q] * 128 + ((lch[q] ^ (lrow[q] & 7)) << 4);
    }

    #define LOAD_STAGE(stage, kElem) do { \
        int _aK = (kElem) < 2*Kp ? (kElem) : (kElem) - 2*Kp; \
        int _wK = (kElem) < Kp   ? (kElem) : (kElem) - Kp; \
        uint32_t sA = sb + (stage) * STAGE_BYTES; \
        uint32_t sW = sA + 16384; \
        _Pragma("unroll") \
        for (int q = 0; q < 4; q++) { \
            int gm = m0 + lrow[q]; \
            cp_async16(sA + lsw[q], Abase + (size_t)gm * 2 * Kp + _aK + lch[q]*8, gm < rows ? 16 : 0); \
            cp_async16(sW + lsw[q], Wbase + (size_t)lrow[q] * 2 * Kp + _wK + lch[q]*8, 16); \
        } \
    } while (0)

    LOAD_STAGE(0, kOff); cp_commit();
    LOAD_STAGE(1, kOff + 64); cp_commit();

    int lane = tid & 31, wid = tid >> 5;
    int wm = wid >> 2, wn = wid & 3;
    float acc[4][4][4];
    #pragma unroll
    for (int a = 0; a < 4; a++)
        #pragma unroll
        for (int b = 0; b < 4; b++)
            #pragma unroll
            for (int c = 0; c < 4; c++) acc[a][b][c] = 0.f;

    int arow_[4];
    #pragma unroll
    for (int mi = 0; mi < 4; mi++) arow_[mi] = wm * 64 + mi * 16 + (lane & 15);
    int ach_ = lane >> 4;
    int brow_[2];
    #pragma unroll
    for (int p = 0; p < 2; p++) brow_[p] = wn * 32 + p * 16 + (lane & 7) + ((lane >> 4) << 3);
    int bch_ = (lane >> 3) & 1;

    for (int i = 0; i < iters; i++) {
        cp_wait1();
        __syncthreads();
        int nf = i + STAGES - 1;
        if (nf < iters) LOAD_STAGE(nf % STAGES, kOff + nf * 64);
        cp_commit();

        uint32_t sA = sb + (i % STAGES) * STAGE_BYTES;
        uint32_t sW = sA + 16384;
        #pragma unroll
        for (int s2 = 0; s2 < 4; s2++) {
            uint32_t af[4][4];
            #pragma unroll
            for (int mi = 0; mi < 4; mi++) {
                int row = arow_[mi];
                int ch = 2 * s2 + ach_;
                uint32_t ad = sA + row * 128 + ((ch ^ (row & 7)) << 4);
                ldsm4(af[mi][0], af[mi][1], af[mi][2], af[mi][3], ad);
            }
            uint32_t b0[4], b1[4];
            #pragma unroll
            for (int p = 0; p < 2; p++) {
                int row = brow_[p];
                int ch = 2 * s2 + bch_;
                uint32_t bd = sW + row * 128 + ((ch ^ (row & 7)) << 4);
                uint32_t r0, r1, r2, r3;
                ldsm4(r0, r1, r2, r3, bd);
                b0[2*p] = r0; b1[2*p] = r1; b0[2*p+1] = r2; b1[2*p+1] = r3;
            }
            #pragma unroll
            for (int mi = 0; mi < 4; mi++)
                #pragma unroll
                for (int ni = 0; ni < 4; ni++)
                    mma_bf16(acc[mi][ni], af[mi], b0[ni], b1[ni]);
        }
        __syncthreads();
    }

    float* Cp = sg.C + (ga.kSplit > 1 ? (size_t)blockIdx.z * RMAX * sg.N : 0);
    int rr = lane >> 2;
    int cc = (lane & 3) * 2;
    #pragma unroll
    for (int mi = 0; mi < 4; mi++) {
        int m1 = m0 + wm * 64 + mi * 16 + rr;
        #pragma unroll
        for (int ni = 0; ni < 4; ni++) {
            int n1 = n0g + wn * 32 + ni * 8 + cc;
            float bx = 0.f, by = 0.f;
            if (sg.bias) { bx = sg.bias[n1]; by = sg.bias[n1 + 1]; }
            if (m1 < rows)
                *(float2*)(Cp + (size_t)m1 * sg.N + n1) =
                    make_float2(acc[mi][ni][0] + bx, acc[mi][ni][1] + by);
            if (m1 + 8 < rows)
                *(float2*)(Cp + (size_t)(m1 + 8) * sg.N + n1) =
                    make_float2(acc[mi][ni][2] + bx, acc[mi][ni][3] + by);
        }
    }
    #undef LOAD_STAGE
}

// ---------------- router / topk / select+map ----------------
__global__ void router_kernel(const float* __restrict__ hs, const float* __restrict__ rwv) {
    int row  = blockIdx.x * 8 + (threadIdx.x >> 5);
    int lane = threadIdx.x & 31;
    if (row >= BSROWS) return;
    const float* x = hs + (size_t)row * D;
    float s = 0.f;
    for (int i = lane; i < D; i += 32) s += x[i] * rwv[i];
    #pragma unroll
    for (int o = 16; o; o >>= 1) s += __shfl_xor_sync(0xffffffffu, s, o);
    if (lane == 0) d_rw[row] = s;
}

__global__ void topk_kernel() {
    __shared__ float s[S];
    int b = blockIdx.x;
    int t = threadIdx.x;
    s[t] = d_rw[b*S + t]; s[t + 1024] = d_rw[b*S + t + 1024];
    for (int k = 2; k <= S; k <<= 1)
        for (int j = k >> 1; j > 0; j >>= 1) {
            __syncthreads();
            for (int i = t; i < S; i += 1024) {
                int ixj = i ^ j;
                if (ixj > i) {
                    bool up = ((i & k) == 0);
                    float a = s[i], c = s[ixj];
                    if ((a > c) == up) { s[i] = c; s[ixj] = a; }
                }
            }
        }
    __syncthreads();
    if (t == 0) d_thresh[b] = s[S - KCAP];
}

__global__ void selmap_kernel() {
    int t = threadIdx.x;                      // 1024 threads
    for (int i = t; i < BSROWS; i += 1024) d_selg[i] = -1;
    int wid = t >> 5, lane = t & 31;
    if (wid < B) {
        int b = wid;
        float th = d_thresh[b];
        int total = 0;
        for (int c = 0; c < S/32; c++) {
            int idx = c*32 + lane;
            bool f = d_rw[b*S + idx] >= th;
            unsigned m = __ballot_sync(0xffffffffu, f);
            int pre = __popc(m & ((1u << lane) - 1u));
            if (f) d_selidx[b*S + total + pre] = idx;
            total += __popc(m);
        }
        if (lane == 0) d_selcnt[b] = total;
    }
    __syncthreads();
    int c0 = d_selcnt[0], c1 = d_selcnt[1];
    int rows = c0 + c1; if (rows > RMAX) rows = RMAX;
    if (t == 0) { d_off[0]=0; d_off[1]=c0; d_off[2]=c0+c1; d_rows[0]=rows; }
    for (int i = t; i < c0; i += 1024) if (i < RMAX) {
        int p = d_selidx[i];
        d_row_b[i] = 0; d_row_p[i] = p; d_selg[p] = i;
    }
    for (int i = t; i < c1; i += 1024) if (c0 + i < RMAX) {
        int p = d_selidx[S + i];
        d_row_b[c0+i] = 1; d_row_p[c0+i] = p; d_selg[S + p] = c0 + i;
    }
}

// ---------------- gather + rmsnorm -> a2 (and d_x) fused ----------------
__global__ void gather_rms_a2_kernel(const float* __restrict__ hs, const float* __restrict__ w) {
    int g = blockIdx.x;
    if (g >= d_rows[0]) return;
    int b = d_row_b[g], p = d_row_p[g];
    const float4* src = (const float4*)(hs + ((size_t)b*S + p) * D);
    float4* dx = (float4*)(d_x + (size_t)g * D);
    float ss = 0.f;
    for (int i = threadIdx.x; i < D/4; i += 256) {
        float4 v = src[i]; dx[i] = v;
        ss += v.x*v.x + v.y*v.y + v.z*v.z + v.w*v.w;
    }
    __shared__ float red[8];
    int lane = threadIdx.x & 31, wid = threadIdx.x >> 5;
    #pragma unroll
    for (int o = 16; o; o >>= 1) ss += __shfl_xor_sync(0xffffffffu, ss, o);
    if (lane == 0) red[wid] = ss;
    __syncthreads();
    if (threadIdx.x == 0) { float v=0.f; for (int i=0;i<8;i++) v+=red[i]; red[0]=v; }
    __syncthreads();
    float inv = rsqrtf(red[0] / (float)D + EPSF);
    __nv_bfloat16* drow = d_a2 + (size_t)g * 2 * D;
    const float4* wv4 = (const float4*)w;
    for (int i = threadIdx.x; i < D/4; i += 256) {
        float4 v = dx[i], ww = wv4[i];
        float4 hv = make_float4(v.x*inv*ww.x, v.y*inv*ww.y, v.z*inv*ww.z, v.w*inv*ww.w);
        uint2 hi, lo; split4(hv, hi, lo);
        *(uint2*)(drow + i*4)     = hi;
        *(uint2*)(drow + D + i*4) = lo;
    }
}

// ---------------- O-reduce(2) + residual + rmsnorm -> a2, updates d_x ----------------
__global__ void rms_reduce_a2_kernel(const float* __restrict__ w) {
    int g = blockIdx.x;
    if (g >= d_rows[0]) return;
    float4* dx = (float4*)(d_x + (size_t)g * D);
    const float4* p0 = (const float4*)(d_part + (size_t)g * D);
    const float4* p1 = (const float4*)(d_part + (size_t)RMAX * D + (size_t)g * D);
    float ss = 0.f;
    for (int i = threadIdx.x; i < D/4; i += 256) {
        float4 v = dx[i], a = p0[i], b = p1[i];
        v.x += a.x + b.x; v.y += a.y + b.y; v.z += a.z + b.z; v.w += a.w + b.w;
        dx[i] = v;
        ss += v.x*v.x + v.y*v.y + v.z*v.z + v.w*v.w;
    }
    __shared__ float red[8];
    int lane = threadIdx.x & 31, wid = threadIdx.x >> 5;
    #pragma unroll
    for (int o = 16; o; o >>= 1) ss += __shfl_xor_sync(0xffffffffu, ss, o);
    if (lane == 0) red[wid] = ss;
    __syncthreads();
    if (threadIdx.x == 0) { float v=0.f; for (int i=0;i<8;i++) v+=red[i]; red[0]=v; }
    __syncthreads();
    float inv = rsqrtf(red[0] / (float)D + EPSF);
    __nv_bfloat16* drow = d_a2 + (size_t)g * 2 * D;
    const float4* wv4 = (const float4*)w;
    for (int i = threadIdx.x; i < D/4; i += 256) {
        float4 v = dx[i], ww = wv4[i];
        float4 hv = make_float4(v.x*inv*ww.x, v.y*inv*ww.y, v.z*inv*ww.z, v.w*inv*ww.w);
        uint2 hi, lo; split4(hv, hi, lo);
        *(uint2*)(drow + i*4)     = hi;
        *(uint2*)(drow + D + i*4) = lo;
    }
}

// ---------------- RoPE ----------------
__global__ void rope_kernel() {
    int g = blockIdx.x;
    if (g >= d_rows[0]) return;
    float fp = (float)d_row_p[g];
    const float L2_10000 = 13.287712379549449f;
    for (int idx = threadIdx.x; idx < (HQ + HKV) * 64; idx += 256) {
        int head = idx >> 6;
        int i = idx & 63;
        float inv = exp2f(-(float)i * (L2_10000 / 64.0f));
        float fr = fp * inv;
        float c = cosf(fr), s = sinf(fr);
        float* ptr;
        if (head < HQ) ptr = d_q + (size_t)g*(HQ*HD) + head*HD;
        else           ptr = d_k + (size_t)g*(HKV*HD) + (head-HQ)*HD;
        float x1 = ptr[i], x2 = ptr[i+64];
        ptr[i]    = x1*c - x2*s;
        ptr[i+64] = x2*c + x1*s;
    }
}

// ---------------- attention -> a2 directly ----------------
__global__ void attn_kernel() {
    int g = blockIdx.x;
    if (g >= d_rows[0]) return;
    int h = threadIdx.y + blockIdx.y * 8;
    int b = d_row_b[g];
    int off = d_off[b];
    int r = g - off;
    int p = d_row_p[g];
    int lane = threadIdx.x;
    int kvh = h >> 1;

    float4 qv = *(const float4*)(d_q + (size_t)g*(HQ*HD) + h*HD + lane*4);
    const float scale = 0.08838834764831843f;

    float m = -INFINITY, l = 0.f;
    float4 acc = make_float4(0.f, 0.f, 0.f, 0.f);

    for (int j = 0; j <= r; j++) {
        const float* kp = d_k + (size_t)(off + j)*(HKV*HD) + kvh*HD;
        float4 kv = *(const float4*)(kp + lane*4);
        float sdot = qv.x*kv.x + qv.y*kv.y + qv.z*kv.z + qv.w*kv.w;
        #pragma unroll
        for (int o = 16; o; o >>= 1) sdot += __shfl_xor_sync(0xffffffffu, sdot, o);
        float sc = sdot * scale;
        float mn = fmaxf(m, sc);
        float eo = expf(m - mn);
        float ec = expf(sc - mn);
        const float* vp = d_v + (size_t)(off + j)*(HKV*HD) + kvh*HD;
        float4 vv = *(const float4*)(vp + lane*4);
        l = l*eo + ec;
        acc.x = acc.x*eo + ec*vv.x;
        acc.y = acc.y*eo + ec*vv.y;
        acc.z = acc.z*eo + ec*vv.z;
        acc.w = acc.w*eo + ec*vv.w;
        m = mn;
    }
    int zc = p - r;
    if (zc > 0) {
        float mn = fmaxf(m, 0.f);
        float eo = expf(m - mn);
        l = l*eo + (float)zc * expf(-mn);
        acc.x *= eo; acc.y *= eo; acc.z *= eo; acc.w *= eo;
    }
    float invl = 1.f / l;
    float4 o4 = make_float4(acc.x*invl, acc.y*invl, acc.z*invl, acc.w*invl);
    uint2 hi, lo; split4(o4, hi, lo);
    __nv_bfloat16* drow = d_a2 + (size_t)g * 2 * D + h * HD + lane * 4;
    *(uint2*)(drow)     = hi;
    *(uint2*)(drow + D) = lo;
}

// ---------------- silu(g)*u -> a2 (K=FF) ----------------
__global__ void silu_a2_kernel() {
    int g = blockIdx.x;
    if (g >= d_rows[0]) return;
    const float4* gr = (const float4*)(d_gg + (size_t)g * FF);
    const float4* ur = (const float4*)(d_uu + (size_t)g * FF);
    __nv_bfloat16* drow = d_a2 + (size_t)g * 2 * FF;
    for (int i = threadIdx.x; i < FF/4; i += 256) {
        float4 x = gr[i], u = ur[i];
        float4 s;
        s.x = (x.x / (1.f + expf(-x.x))) * u.x;
        s.y = (x.y / (1.f + expf(-x.y))) * u.y;
        s.z = (x.z / (1.f + expf(-x.z))) * u.z;
        s.w = (x.w / (1.f + expf(-x.w))) * u.w;
        uint2 hi, lo; split4(s, hi, lo);
        *(uint2*)(drow + i*4)      = hi;
        *(uint2*)(drow + FF + i*4) = lo;
    }
}

// ---------------- fused output: passthrough OR (residual + down-reduce(4)) * rw ----------------
__global__ void out_kernel(const float* __restrict__ hs, float* __restrict__ out) {
    int r = blockIdx.x;
    int g = d_selg[r];
    const float4* src = (const float4*)(hs + (size_t)r * D);
    float4* dst = (float4*)(out + (size_t)r * D);
    if (g < 0) {
        for (int i = threadIdx.x; i < D/4; i += 256) dst[i] = src[i];
    } else {
        float sc = d_rw[r];
        const float4* xs = (const float4*)(d_x + (size_t)g * D);
        const float4* p0 = (const float4*)(d_part + (size_t)g * D);
        const float4* p1 = (const float4*)(d_part + (size_t)RMAX * D + (size_t)g * D);
        const float4* p2 = (const float4*)(d_part + (size_t)2 * RMAX * D + (size_t)g * D);
        const float4* p3 = (const float4*)(d_part + (size_t)3 * RMAX * D + (size_t)g * D);
        for (int i = threadIdx.x; i < D/4; i += 256) {
            float4 v = xs[i], a = p0[i], b = p1[i], c = p2[i], d = p3[i];
            v.x = (v.x + a.x + b.x + c.x + d.x) * sc;
            v.y = (v.y + a.y + b.y + c.y + d.y) * sc;
            v.z = (v.z + a.z + b.z + c.z + d.z) * sc;
            v.w = (v.w + a.w + b.w + c.w + d.w) * sc;
            dst[i] = v;
        }
    }
}

// ---------------- launch ----------------
extern "C" void kernel_launch(void* const* d_in, const int* in_sizes, int n_in,
                              void* d_out, int out_size) {
    const float* hs    = (const float*)d_in[0];
    const float* rwv   = (const float*)d_in[1];
    const float* wq    = (const float*)d_in[2];
    const float* bq    = (const float*)d_in[3];
    const float* wk    = (const float*)d_in[4];
    const float* bk    = (const float*)d_in[5];
    const float* wv    = (const float*)d_in[6];
    const float* bv    = (const float*)d_in[7];
    const float* wo    = (const float*)d_in[8];
    const float* wgate = (const float*)d_in[9];
    const float* wup   = (const float*)d_in[10];
    const float* wdown = (const float*)d_in[11];
    const float* ln1w  = (const float*)d_in[12];
    const float* ln2w  = (const float*)d_in[13];
    float* out = (float*)d_out;

    float *px, *pq, *pk, *pv, *pg, *pu, *ppart;
    __nv_bfloat16 *pw2, *pa2;
    cudaGetSymbolAddress((void**)&px,    d_x);
    cudaGetSymbolAddress((void**)&pq,    d_q);
    cudaGetSymbolAddress((void**)&pk,    d_k);
    cudaGetSymbolAddress((void**)&pv,    d_v);
    cudaGetSymbolAddress((void**)&pg,    d_gg);
    cudaGetSymbolAddress((void**)&pu,    d_uu);
    cudaGetSymbolAddress((void**)&pw2,   d_w2);
    cudaGetSymbolAddress((void**)&pa2,   d_a2);
    cudaGetSymbolAddress((void**)&ppart, d_part);

    static int attr_done = 0;
    if (!attr_done) {
        cudaFuncSetAttribute(mma_gemm, cudaFuncAttributeMaxDynamicSharedMemorySize, SM_TOTAL);
        attr_done = 1;
    }

    router_kernel<<<BSROWS/8, 256>>>(hs, rwv);
    topk_kernel<<<B, 1024>>>();
    selmap_kernel<<<1, 1024>>>();
    gather_rms_a2_kernel<<<RMAX, 256>>>(hs, ln1w);

    // all weight conversions in one launch
    {
        WAll wa;
        wa.s[0] = { wq,    pw2 + OFF_WQ, 2048*(D/8),  8,  D };
        wa.s[1] = { wk,    pw2 + OFF_WK, 1024*(D/8),  8,  D };
        wa.s[2] = { wv,    pw2 + OFF_WV, 1024*(D/8),  8,  D };
        wa.s[3] = { wo,    pw2 + OFF_WO, 2048*(D/8),  8,  D };
        wa.s[4] = { wgate, pw2 + OFF_WG, 8192*(D/8),  8,  D };
        wa.s[5] = { wup,   pw2 + OFF_WU, 8192*(D/8),  8,  D };
        wa.s[6] = { wdown, pw2 + OFF_WD, 2048*(FF/8), 10, FF };
        convert_all_kernel<<<2368, 256>>>(wa);
    }

    // QKV GEMM
    {
        GArgs ga = {};
        ga.A2 = pa2; ga.K = D; ga.kSplit = 1; ga.nseg = 3;
        ga.s[0] = { pw2 + OFF_WQ, bq, pq, HQ*HD,  16 };
        ga.s[1] = { pw2 + OFF_WK, bk, pk, HKV*HD, 8  };
        ga.s[2] = { pw2 + OFF_WV, bv, pv, HKV*HD, 8  };
        mma_gemm<<<dim3(32, 4, 1), 256, SM_TOTAL>>>(ga);
    }
    rope_kernel<<<RMAX, 256>>>();
    attn_kernel<<<dim3(RMAX, HQ/8), dim3(32, 8)>>>();
    // O projection, split-K 2 -> partials
    {
        GArgs ga = {};
        ga.A2 = pa2; ga.K = D; ga.kSplit = 2; ga.nseg = 1;
        ga.s[0] = { pw2 + OFF_WO, nullptr, ppart, D, 16 };
        mma_gemm<<<dim3(16, 4, 2), 256, SM_TOTAL>>>(ga);
    }
    // fused: reduce(2) + residual + rmsnorm2 -> a2 (updates d_x)
    rms_reduce_a2_kernel<<<RMAX, 256>>>(ln2w);
    // gate + up merged
    {
        GArgs ga = {};
        ga.A2 = pa2; ga.K = D; ga.kSplit = 1; ga.nseg = 2;
        ga.s[0] = { pw2 + OFF_WG, nullptr, pg, FF, 64 };
        ga.s[1] = { pw2 + OFF_WU, nullptr, pu, FF, 64 };
        mma_gemm<<<dim3(128, 4, 1), 256, SM_TOTAL>>>(ga);
    }
    silu_a2_kernel<<<RMAX, 256>>>();
    // down, split-K 4 -> partials (reduced in out_kernel)
    {
        GArgs ga = {};
        ga.A2 = pa2; ga.K = FF; ga.kSplit = 4; ga.nseg = 1;
        ga.s[0] = { pw2 + OFF_WD, nullptr, ppart, D, 16 };
        mma_gemm<<<dim3(16, 4, 4), 256, SM_TOTAL>>>(ga);
    }

    // fused output: passthrough or (d_x + Σ parts) * rw
    out_kernel<<<BSROWS, 256>>>(hs, out);
}

// round 11
// speedup vs baseline: 1.1193x; 1.0198x over previous
#include <cuda_runtime.h>
#include <cuda_bf16.h>
#include <math.h>
#include <stdint.h>

// ---------------- problem constants ----------------
#define B   2
#define S   2048
#define D   2048
#define HQ  16
#define HKV 8
#define HD  128
#define FF  8192
#define KCAP 256
#define BSROWS (B*S)          // 4096
#define RMAX 512
#define EPSF 1e-6f

// ---------------- device scratch ----------------
__device__ float d_rw[BSROWS];
__device__ float d_thresh[B];
__device__ int   d_selidx[BSROWS];
__device__ int   d_selcnt[B];
__device__ int   d_off[B+1];
__device__ int   d_rows[1];
__device__ int   d_row_b[RMAX];
__device__ int   d_row_p[RMAX];
__device__ int   d_selg[BSROWS];
__device__ float d_x   [(size_t)RMAX*D];
__device__ float d_q   [(size_t)RMAX*HQ*HD];
__device__ float d_k   [(size_t)RMAX*HKV*HD];
__device__ float d_v   [(size_t)RMAX*HKV*HD];
__device__ float d_gg  [(size_t)RMAX*FF];
__device__ float d_uu  [(size_t)RMAX*FF];
__device__ float d_part[(size_t)4*RMAX*D];

// compact split-bf16 [hi|lo] (2K per row) weights and activations
#define OFF_WQ 0
#define OFF_WK (OFF_WQ + (size_t)2048*2*D)
#define OFF_WV (OFF_WK + (size_t)1024*2*D)
#define OFF_WO (OFF_WV + (size_t)1024*2*D)
#define OFF_WG (OFF_WO + (size_t)2048*2*D)
#define OFF_WU (OFF_WG + (size_t)8192*2*D)
#define OFF_WD (OFF_WU + (size_t)8192*2*D)
#define W2_TOTAL (OFF_WD + (size_t)2048*2*FF)
__device__ __nv_bfloat16 d_w2[W2_TOTAL];
__device__ __nv_bfloat16 d_a2[(size_t)RMAX*2*FF];

// ---------------- helpers ----------------
__device__ __forceinline__ uint32_t smem_to_u32(const void* p) {
    uint32_t a;
    asm("{ .reg .u64 t; cvta.to.shared.u64 t, %1; cvt.u32.u64 %0, t; }" : "=r"(a) : "l"(p));
    return a;
}
__device__ __forceinline__ void cp_async16(uint32_t dst, const void* src, int sz) {
    asm volatile("cp.async.cg.shared.global [%0], [%1], 16, %2;"
                 :: "r"(dst), "l"(src), "r"(sz) : "memory");
}
__device__ __forceinline__ void cp_commit() { asm volatile("cp.async.commit_group;" ::: "memory"); }
__device__ __forceinline__ void cp_wait1()  { asm volatile("cp.async.wait_group 1;" ::: "memory"); }
__device__ __forceinline__ void ldsm4(uint32_t& r0, uint32_t& r1, uint32_t& r2, uint32_t& r3, uint32_t a) {
    asm volatile("ldmatrix.sync.aligned.m8n8.x4.shared.b16 {%0,%1,%2,%3}, [%4];"
                 : "=r"(r0), "=r"(r1), "=r"(r2), "=r"(r3) : "r"(a));
}
__device__ __forceinline__ void mma_bf16(float* c, const uint32_t* a, uint32_t b0, uint32_t b1) {
    asm volatile("mma.sync.aligned.m16n8k16.row.col.f32.bf16.bf16.f32 "
                 "{%0,%1,%2,%3}, {%4,%5,%6,%7}, {%8,%9}, {%0,%1,%2,%3};"
                 : "+f"(c[0]), "+f"(c[1]), "+f"(c[2]), "+f"(c[3])
                 : "r"(a[0]), "r"(a[1]), "r"(a[2]), "r"(a[3]), "r"(b0), "r"(b1));
}
__device__ __forceinline__ uint32_t pack_bf2(float a, float b) {
    __nv_bfloat162 t = __floats2bfloat162_rn(a, b);
    return *(uint32_t*)&t;
}
__device__ __forceinline__ void split4(float4 v, uint2& hi, uint2& lo) {
    float h0 = __bfloat162float(__float2bfloat16(v.x));
    float h1 = __bfloat162float(__float2bfloat16(v.y));
    float h2 = __bfloat162float(__float2bfloat16(v.z));
    float h3 = __bfloat162float(__float2bfloat16(v.w));
    hi = make_uint2(pack_bf2(h0,h1), pack_bf2(h2,h3));
    lo = make_uint2(pack_bf2(v.x-h0, v.y-h1), pack_bf2(v.z-h2, v.w-h3));
}

// ---------------- merged weight conversion (7 segments) ----------------
struct WSeg { const float* src; __nv_bfloat16* dst; int total; int kshift; int K; };
struct WAll { WSeg s[7]; };

__global__ void convert_all_kernel(WAll wa) {
    #pragma unroll 1
    for (int sgi = 0; sgi < 7; sgi++) {
        const float* __restrict__ src = wa.s[sgi].src;
        __nv_bfloat16* __restrict__ dst = wa.s[sgi].dst;
        int K = wa.s[sgi].K;
        int ks = wa.s[sgi].kshift;
        int total = wa.s[sgi].total;
        int kmask = (1 << ks) - 1;
        for (int idx = blockIdx.x * 256 + threadIdx.x; idx < total; idx += gridDim.x * 256) {
            int n = idx >> ks, c8 = (idx & kmask) << 3;
            const float* sp = src + (size_t)n * K + c8;
            float4 v0 = *(const float4*)(sp);
            float4 v1 = *(const float4*)(sp + 4);
            uint2 hiA, loA, hiB, loB;
            split4(v0, hiA, loA);
            split4(v1, hiB, loB);
            size_t b = (size_t)n * 2 * K + c8;
            *(uint4*)(dst + b)     = make_uint4(hiA.x, hiA.y, hiB.x, hiB.y);
            *(uint4*)(dst + b + K) = make_uint4(loA.x, loA.y, loB.x, loB.y);
        }
    }
}

// ---------------- tensor-core GEMM (round-9 config + forced occupancy 2) ----------------
// Virtual K3 = 3K: vA(k)=k<2K?k:k-2K over A2=[hi|lo]; vW(k)=k<K?k:k-K over W2=[hi|lo].
// CTA tile 128x128, 256 threads (2x4 warps, 64x32 warp tile), BK=64, 3-stage cp.async.
struct Seg { const __nv_bfloat16* W2; const float* bias; float* C; int N; int ntiles; };
struct GArgs { const __nv_bfloat16* A2; int K; int kSplit; int nseg; Seg s[3]; };

#define STAGES 3
#define STAGE_BYTES 32768   // A 16KB + W 16KB (128 rows x 128 bytes each)
#define SM_TOTAL (STAGES*STAGE_BYTES)

__global__ void __launch_bounds__(256, 2) mma_gemm(GArgs ga) {
    extern __shared__ char smem[];
    uint32_t sb = smem_to_u32(smem);
    int tid = threadIdx.x;
    int rows = d_rows[0]; if (rows > RMAX) rows = RMAX;
    int m0 = blockIdx.y * 128;
    int Kp = ga.K;
    int K3 = 3 * Kp;

    Seg sg = ga.s[0];
    int nt = blockIdx.x;
    if (ga.nseg > 1 && nt >= ga.s[0].ntiles) {
        nt -= ga.s[0].ntiles; sg = ga.s[1];
        if (ga.nseg > 2 && nt >= ga.s[1].ntiles) { nt -= ga.s[1].ntiles; sg = ga.s[2]; }
    }
    int n0g = nt * 128;
    int kLen = K3 / ga.kSplit;
    int kOff = blockIdx.z * kLen;
    int iters = kLen / 64;

    const __nv_bfloat16* Abase = ga.A2;
    const __nv_bfloat16* Wbase = sg.W2 + (size_t)n0g * 2 * Kp;

    int lrow[4], lch[4]; uint32_t lsw[4];
    #pragma unroll
    for (int q = 0; q < 4; q++) {
        int j = tid + q * 256;
        lrow[q] = j >> 3; lch[q] = j & 7;
        lsw[q] = lrow[q] * 128 + ((lch[q] ^ (lrow[q] & 7)) << 4);
    }

    #define LOAD_STAGE(stage, kElem) do { \
        int _aK = (kElem) < 2*Kp ? (kElem) : (kElem) - 2*Kp; \
        int _wK = (kElem) < Kp   ? (kElem) : (kElem) - Kp; \
        uint32_t sA = sb + (stage) * STAGE_BYTES; \
        uint32_t sW = sA + 16384; \
        _Pragma("unroll") \
        for (int q = 0; q < 4; q++) { \
            int gm = m0 + lrow[q]; \
            cp_async16(sA + lsw[q], Abase + (size_t)gm * 2 * Kp + _aK + lch[q]*8, gm < rows ? 16 : 0); \
            cp_async16(sW + lsw[q], Wbase + (size_t)lrow[q] * 2 * Kp + _wK + lch[q]*8, 16); \
        } \
    } while (0)

    LOAD_STAGE(0, kOff); cp_commit();
    LOAD_STAGE(1, kOff + 64); cp_commit();

    int lane = tid & 31, wid = tid >> 5;
    int wm = wid >> 2, wn = wid & 3;
    float acc[4][4][4];
    #pragma unroll
    for (int a = 0; a < 4; a++)
        #pragma unroll
        for (int b = 0; b < 4; b++)
            #pragma unroll
            for (int c = 0; c < 4; c++) acc[a][b][c] = 0.f;

    int arow_[4];
    #pragma unroll
    for (int mi = 0; mi < 4; mi++) arow_[mi] = wm * 64 + mi * 16 + (lane & 15);
    int ach_ = lane >> 4;
    int brow_[2];
    #pragma unroll
    for (int p = 0; p < 2; p++) brow_[p] = wn * 32 + p * 16 + (lane & 7) + ((lane >> 4) << 3);
    int bch_ = (lane >> 3) & 1;

    for (int i = 0; i < iters; i++) {
        cp_wait1();
        __syncthreads();
        int nf = i + STAGES - 1;
        if (nf < iters) LOAD_STAGE(nf % STAGES, kOff + nf * 64);
        cp_commit();

        uint32_t sA = sb + (i % STAGES) * STAGE_BYTES;
        uint32_t sW = sA + 16384;
        #pragma unroll
        for (int s2 = 0; s2 < 4; s2++) {
            uint32_t af[4][4];
            #pragma unroll
            for (int mi = 0; mi < 4; mi++) {
                int row = arow_[mi];
                int ch = 2 * s2 + ach_;
                uint32_t ad = sA + row * 128 + ((ch ^ (row & 7)) << 4);
                ldsm4(af[mi][0], af[mi][1], af[mi][2], af[mi][3], ad);
            }
            uint32_t b0[4], b1[4];
            #pragma unroll
            for (int p = 0; p < 2; p++) {
                int row = brow_[p];
                int ch = 2 * s2 + bch_;
                uint32_t bd = sW + row * 128 + ((ch ^ (row & 7)) << 4);
                uint32_t r0, r1, r2, r3;
                ldsm4(r0, r1, r2, r3, bd);
                b0[2*p] = r0; b1[2*p] = r1; b0[2*p+1] = r2; b1[2*p+1] = r3;
            }
            #pragma unroll
            for (int mi = 0; mi < 4; mi++)
                #pragma unroll
                for (int ni = 0; ni < 4; ni++)
                    mma_bf16(acc[mi][ni], af[mi], b0[ni], b1[ni]);
        }
        __syncthreads();
    }

    float* Cp = sg.C + (ga.kSplit > 1 ? (size_t)blockIdx.z * RMAX * sg.N : 0);
    int rr = lane >> 2;
    int cc = (lane & 3) * 2;
    #pragma unroll
    for (int mi = 0; mi < 4; mi++) {
        int m1 = m0 + wm * 64 + mi * 16 + rr;
        #pragma unroll
        for (int ni = 0; ni < 4; ni++) {
            int n1 = n0g + wn * 32 + ni * 8 + cc;
            float bx = 0.f, by = 0.f;
            if (sg.bias) { bx = sg.bias[n1]; by = sg.bias[n1 + 1]; }
            if (m1 < rows)
                *(float2*)(Cp + (size_t)m1 * sg.N + n1) =
                    make_float2(acc[mi][ni][0] + bx, acc[mi][ni][1] + by);
            if (m1 + 8 < rows)
                *(float2*)(Cp + (size_t)(m1 + 8) * sg.N + n1) =
                    make_float2(acc[mi][ni][2] + bx, acc[mi][ni][3] + by);
        }
    }
    #undef LOAD_STAGE
}

// ---------------- router / topk / select+map ----------------
__global__ void router_kernel(const float* __restrict__ hs, const float* __restrict__ rwv) {
    int row  = blockIdx.x * 8 + (threadIdx.x >> 5);
    int lane = threadIdx.x & 31;
    if (row >= BSROWS) return;
    const float* x = hs + (size_t)row * D;
    float s = 0.f;
    for (int i = lane; i < D; i += 32) s += x[i] * rwv[i];
    #pragma unroll
    for (int o = 16; o; o >>= 1) s += __shfl_xor_sync(0xffffffffu, s, o);
    if (lane == 0) d_rw[row] = s;
}

__global__ void topk_kernel() {
    __shared__ float s[S];
    int b = blockIdx.x;
    int t = threadIdx.x;
    s[t] = d_rw[b*S + t]; s[t + 1024] = d_rw[b*S + t + 1024];
    for (int k = 2; k <= S; k <<= 1)
        for (int j = k >> 1; j > 0; j >>= 1) {
            __syncthreads();
            for (int i = t; i < S; i += 1024) {
                int ixj = i ^ j;
                if (ixj > i) {
                    bool up = ((i & k) == 0);
                    float a = s[i], c = s[ixj];
                    if ((a > c) == up) { s[i] = c; s[ixj] = a; }
                }
            }
        }
    __syncthreads();
    if (t == 0) d_thresh[b] = s[S - KCAP];
}

__global__ void selmap_kernel() {
    int t = threadIdx.x;                      // 1024 threads
    for (int i = t; i < BSROWS; i += 1024) d_selg[i] = -1;
    int wid = t >> 5, lane = t & 31;
    if (wid < B) {
        int b = wid;
        float th = d_thresh[b];
        int total = 0;
        for (int c = 0; c < S/32; c++) {
            int idx = c*32 + lane;
            bool f = d_rw[b*S + idx] >= th;
            unsigned m = __ballot_sync(0xffffffffu, f);
            int pre = __popc(m & ((1u << lane) - 1u));
            if (f) d_selidx[b*S + total + pre] = idx;
            total += __popc(m);
        }
        if (lane == 0) d_selcnt[b] = total;
    }
    __syncthreads();
    int c0 = d_selcnt[0], c1 = d_selcnt[1];
    int rows = c0 + c1; if (rows > RMAX) rows = RMAX;
    if (t == 0) { d_off[0]=0; d_off[1]=c0; d_off[2]=c0+c1; d_rows[0]=rows; }
    for (int i = t; i < c0; i += 1024) if (i < RMAX) {
        int p = d_selidx[i];
        d_row_b[i] = 0; d_row_p[i] = p; d_selg[p] = i;
    }
    for (int i = t; i < c1; i += 1024) if (c0 + i < RMAX) {
        int p = d_selidx[S + i];
        d_row_b[c0+i] = 1; d_row_p[c0+i] = p; d_selg[S + p] = c0 + i;
    }
}

// ---------------- gather + rmsnorm -> a2 (and d_x) fused ----------------
__global__ void gather_rms_a2_kernel(const float* __restrict__ hs, const float* __restrict__ w) {
    int g = blockIdx.x;
    if (g >= d_rows[0]) return;
    int b = d_row_b[g], p = d_row_p[g];
    const float4* src = (const float4*)(hs + ((size_t)b*S + p) * D);
    float4* dx = (float4*)(d_x + (size_t)g * D);
    float ss = 0.f;
    for (int i = threadIdx.x; i < D/4; i += 256) {
        float4 v = src[i]; dx[i] = v;
        ss += v.x*v.x + v.y*v.y + v.z*v.z + v.w*v.w;
    }
    __shared__ float red[8];
    int lane = threadIdx.x & 31, wid = threadIdx.x >> 5;
    #pragma unroll
    for (int o = 16; o; o >>= 1) ss += __shfl_xor_sync(0xffffffffu, ss, o);
    if (lane == 0) red[wid] = ss;
    __syncthreads();
    if (threadIdx.x == 0) { float v=0.f; for (int i=0;i<8;i++) v+=red[i]; red[0]=v; }
    __syncthreads();
    float inv = rsqrtf(red[0] / (float)D + EPSF);
    __nv_bfloat16* drow = d_a2 + (size_t)g * 2 * D;
    const float4* wv4 = (const float4*)w;
    for (int i = threadIdx.x; i < D/4; i += 256) {
        float4 v = dx[i], ww = wv4[i];
        float4 hv = make_float4(v.x*inv*ww.x, v.y*inv*ww.y, v.z*inv*ww.z, v.w*inv*ww.w);
        uint2 hi, lo; split4(hv, hi, lo);
        *(uint2*)(drow + i*4)     = hi;
        *(uint2*)(drow + D + i*4) = lo;
    }
}

// ---------------- O-reduce(2) + residual + rmsnorm -> a2, updates d_x ----------------
__global__ void rms_reduce_a2_kernel(const float* __restrict__ w) {
    int g = blockIdx.x;
    if (g >= d_rows[0]) return;
    float4* dx = (float4*)(d_x + (size_t)g * D);
    const float4* p0 = (const float4*)(d_part + (size_t)g * D);
    const float4* p1 = (const float4*)(d_part + (size_t)RMAX * D + (size_t)g * D);
    float ss = 0.f;
    for (int i = threadIdx.x; i < D/4; i += 256) {
        float4 v = dx[i], a = p0[i], b = p1[i];
        v.x += a.x + b.x; v.y += a.y + b.y; v.z += a.z + b.z; v.w += a.w + b.w;
        dx[i] = v;
        ss += v.x*v.x + v.y*v.y + v.z*v.z + v.w*v.w;
    }
    __shared__ float red[8];
    int lane = threadIdx.x & 31, wid = threadIdx.x >> 5;
    #pragma unroll
    for (int o = 16; o; o >>= 1) ss += __shfl_xor_sync(0xffffffffu, ss, o);
    if (lane == 0) red[wid] = ss;
    __syncthreads();
    if (threadIdx.x == 0) { float v=0.f; for (int i=0;i<8;i++) v+=red[i]; red[0]=v; }
    __syncthreads();
    float inv = rsqrtf(red[0] / (float)D + EPSF);
    __nv_bfloat16* drow = d_a2 + (size_t)g * 2 * D;
    const float4* wv4 = (const float4*)w;
    for (int i = threadIdx.x; i < D/4; i += 256) {
        float4 v = dx[i], ww = wv4[i];
        float4 hv = make_float4(v.x*inv*ww.x, v.y*inv*ww.y, v.z*inv*ww.z, v.w*inv*ww.w);
        uint2 hi, lo; split4(hv, hi, lo);
        *(uint2*)(drow + i*4)     = hi;
        *(uint2*)(drow + D + i*4) = lo;
    }
}

// ---------------- RoPE ----------------
__global__ void rope_kernel() {
    int g = blockIdx.x;
    if (g >= d_rows[0]) return;
    float fp = (float)d_row_p[g];
    const float L2_10000 = 13.287712379549449f;
    for (int idx = threadIdx.x; idx < (HQ + HKV) * 64; idx += 256) {
        int head = idx >> 6;
        int i = idx & 63;
        float inv = exp2f(-(float)i * (L2_10000 / 64.0f));
        float fr = fp * inv;
        float c = cosf(fr), s = sinf(fr);
        float* ptr;
        if (head < HQ) ptr = d_q + (size_t)g*(HQ*HD) + head*HD;
        else           ptr = d_k + (size_t)g*(HKV*HD) + (head-HQ)*HD;
        float x1 = ptr[i], x2 = ptr[i+64];
        ptr[i]    = x1*c - x2*s;
        ptr[i+64] = x2*c + x1*s;
    }
}

// ---------------- attention -> a2 directly ----------------
__global__ void attn_kernel() {
    int g = blockIdx.x;
    if (g >= d_rows[0]) return;
    int h = threadIdx.y + blockIdx.y * 8;
    int b = d_row_b[g];
    int off = d_off[b];
    int r = g - off;
    int p = d_row_p[g];
    int lane = threadIdx.x;
    int kvh = h >> 1;

    float4 qv = *(const float4*)(d_q + (size_t)g*(HQ*HD) + h*HD + lane*4);
    const float scale = 0.08838834764831843f;

    float m = -INFINITY, l = 0.f;
    float4 acc = make_float4(0.f, 0.f, 0.f, 0.f);

    for (int j = 0; j <= r; j++) {
        const float* kp = d_k + (size_t)(off + j)*(HKV*HD) + kvh*HD;
        float4 kv = *(const float4*)(kp + lane*4);
        float sdot = qv.x*kv.x + qv.y*kv.y + qv.z*kv.z + qv.w*kv.w;
        #pragma unroll
        for (int o = 16; o; o >>= 1) sdot += __shfl_xor_sync(0xffffffffu, sdot, o);
        float sc = sdot * scale;
        float mn = fmaxf(m, sc);
        float eo = expf(m - mn);
        float ec = expf(sc - mn);
        const float* vp = d_v + (size_t)(off + j)*(HKV*HD) + kvh*HD;
        float4 vv = *(const float4*)(vp + lane*4);
        l = l*eo + ec;
        acc.x = acc.x*eo + ec*vv.x;
        acc.y = acc.y*eo + ec*vv.y;
        acc.z = acc.z*eo + ec*vv.z;
        acc.w = acc.w*eo + ec*vv.w;
        m = mn;
    }
    int zc = p - r;
    if (zc > 0) {
        float mn = fmaxf(m, 0.f);
        float eo = expf(m - mn);
        l = l*eo + (float)zc * expf(-mn);
        acc.x *= eo; acc.y *= eo; acc.z *= eo; acc.w *= eo;
    }
    float invl = 1.f / l;
    float4 o4 = make_float4(acc.x*invl, acc.y*invl, acc.z*invl, acc.w*invl);
    uint2 hi, lo; split4(o4, hi, lo);
    __nv_bfloat16* drow = d_a2 + (size_t)g * 2 * D + h * HD + lane * 4;
    *(uint2*)(drow)     = hi;
    *(uint2*)(drow + D) = lo;
}

// ---------------- silu(g)*u -> a2 (K=FF) ----------------
__global__ void silu_a2_kernel() {
    int g = blockIdx.x;
    if (g >= d_rows[0]) return;
    const float4* gr = (const float4*)(d_gg + (size_t)g * FF);
    const float4* ur = (const float4*)(d_uu + (size_t)g * FF);
    __nv_bfloat16* drow = d_a2 + (size_t)g * 2 * FF;
    for (int i = threadIdx.x; i < FF/4; i += 256) {
        float4 x = gr[i], u = ur[i];
        float4 s;
        s.x = (x.x / (1.f + expf(-x.x))) * u.x;
        s.y = (x.y / (1.f + expf(-x.y))) * u.y;
        s.z = (x.z / (1.f + expf(-x.z))) * u.z;
        s.w = (x.w / (1.f + expf(-x.w))) * u.w;
        uint2 hi, lo; split4(s, hi, lo);
        *(uint2*)(drow + i*4)      = hi;
        *(uint2*)(drow + FF + i*4) = lo;
    }
}

// ---------------- fused output: passthrough OR (residual + down-reduce(4)) * rw ----------------
__global__ void out_kernel(const float* __restrict__ hs, float* __restrict__ out) {
    int r = blockIdx.x;
    int g = d_selg[r];
    const float4* src = (const float4*)(hs + (size_t)r * D);
    float4* dst = (float4*)(out + (size_t)r * D);
    if (g < 0) {
        for (int i = threadIdx.x; i < D/4; i += 256) dst[i] = src[i];
    } else {
        float sc = d_rw[r];
        const float4* xs = (const float4*)(d_x + (size_t)g * D);
        const float4* p0 = (const float4*)(d_part + (size_t)g * D);
        const float4* p1 = (const float4*)(d_part + (size_t)RMAX * D + (size_t)g * D);
        const float4* p2 = (const float4*)(d_part + (size_t)2 * RMAX * D + (size_t)g * D);
        const float4* p3 = (const float4*)(d_part + (size_t)3 * RMAX * D + (size_t)g * D);
        for (int i = threadIdx.x; i < D/4; i += 256) {
            float4 v = xs[i], a = p0[i], b = p1[i], c = p2[i], d = p3[i];
            v.x = (v.x + a.x + b.x + c.x + d.x) * sc;
            v.y = (v.y + a.y + b.y + c.y + d.y) * sc;
            v.z = (v.z + a.z + b.z + c.z + d.z) * sc;
            v.w = (v.w + a.w + b.w + c.w + d.w) * sc;
            dst[i] = v;
        }
    }
}

// ---------------- launch ----------------
extern "C" void kernel_launch(void* const* d_in, const int* in_sizes, int n_in,
                              void* d_out, int out_size) {
    const float* hs    = (const float*)d_in[0];
    const float* rwv   = (const float*)d_in[1];
    const float* wq    = (const float*)d_in[2];
    const float* bq    = (const float*)d_in[3];
    const float* wk    = (const float*)d_in[4];
    const float* bk    = (const float*)d_in[5];
    const float* wv    = (const float*)d_in[6];
    const float* bv    = (const float*)d_in[7];
    const float* wo    = (const float*)d_in[8];
    const float* wgate = (const float*)d_in[9];
    const float* wup   = (const float*)d_in[10];
    const float* wdown = (const float*)d_in[11];
    const float* ln1w  = (const float*)d_in[12];
    const float* ln2w  = (const float*)d_in[13];
    float* out = (float*)d_out;

    float *px, *pq, *pk, *pv, *pg, *pu, *ppart;
    __nv_bfloat16 *pw2, *pa2;
    cudaGetSymbolAddress((void**)&px,    d_x);
    cudaGetSymbolAddress((void**)&pq,    d_q);
    cudaGetSymbolAddress((void**)&pk,    d_k);
    cudaGetSymbolAddress((void**)&pv,    d_v);
    cudaGetSymbolAddress((void**)&pg,    d_gg);
    cudaGetSymbolAddress((void**)&pu,    d_uu);
    cudaGetSymbolAddress((void**)&pw2,   d_w2);
    cudaGetSymbolAddress((void**)&pa2,   d_a2);
    cudaGetSymbolAddress((void**)&ppart, d_part);

    static int attr_done = 0;
    if (!attr_done) {
        cudaFuncSetAttribute(mma_gemm, cudaFuncAttributeMaxDynamicSharedMemorySize, SM_TOTAL);
        attr_done = 1;
    }

    router_kernel<<<BSROWS/8, 256>>>(hs, rwv);
    topk_kernel<<<B, 1024>>>();
    selmap_kernel<<<1, 1024>>>();
    gather_rms_a2_kernel<<<RMAX, 256>>>(hs, ln1w);

    // all weight conversions in one launch
    {
        WAll wa;
        wa.s[0] = { wq,    pw2 + OFF_WQ, 2048*(D/8),  8,  D };
        wa.s[1] = { wk,    pw2 + OFF_WK, 1024*(D/8),  8,  D };
        wa.s[2] = { wv,    pw2 + OFF_WV, 1024*(D/8),  8,  D };
        wa.s[3] = { wo,    pw2 + OFF_WO, 2048*(D/8),  8,  D };
        wa.s[4] = { wgate, pw2 + OFF_WG, 8192*(D/8),  8,  D };
        wa.s[5] = { wup,   pw2 + OFF_WU, 8192*(D/8),  8,  D };
        wa.s[6] = { wdown, pw2 + OFF_WD, 2048*(FF/8), 10, FF };
        convert_all_kernel<<<2368, 256>>>(wa);
    }

    // QKV GEMM
    {
        GArgs ga = {};
        ga.A2 = pa2; ga.K = D; ga.kSplit = 1; ga.nseg = 3;
        ga.s[0] = { pw2 + OFF_WQ, bq, pq, HQ*HD,  16 };
        ga.s[1] = { pw2 + OFF_WK, bk, pk, HKV*HD, 8  };
        ga.s[2] = { pw2 + OFF_WV, bv, pv, HKV*HD, 8  };
        mma_gemm<<<dim3(32, 4, 1), 256, SM_TOTAL>>>(ga);
    }
    rope_kernel<<<RMAX, 256>>>();
    attn_kernel<<<dim3(RMAX, HQ/8), dim3(32, 8)>>>();
    // O projection, split-K 2 -> partials
    {
        GArgs ga = {};
        ga.A2 = pa2; ga.K = D; ga.kSplit = 2; ga.nseg = 1;
        ga.s[0] = { pw2 + OFF_WO, nullptr, ppart, D, 16 };
        mma_gemm<<<dim3(16, 4, 2), 256, SM_TOTAL>>>(ga);
    }
    // fused: reduce(2) + residual + rmsnorm2 -> a2 (updates d_x)
    rms_reduce_a2_kernel<<<RMAX, 256>>>(ln2w);
    // gate + up merged
    {
        GArgs ga = {};
        ga.A2 = pa2; ga.K = D; ga.kSplit = 1; ga.nseg = 2;
        ga.s[0] = { pw2 + OFF_WG, nullptr, pg, FF, 64 };
        ga.s[1] = { pw2 + OFF_WU, nullptr, pu, FF, 64 };
        mma_gemm<<<dim3(128, 4, 1), 256, SM_TOTAL>>>(ga);
    }
    silu_a2_kernel<<<RMAX, 256>>>();
    // down, split-K 4 -> partials (reduced in out_kernel)
    {
        GArgs ga = {};
        ga.A2 = pa2; ga.K = FF; ga.kSplit = 4; ga.nseg = 1;
        ga.s[0] = { pw2 + OFF_WD, nullptr, ppart, D, 16 };
        mma_gemm<<<dim3(16, 4, 4), 256, SM_TOTAL>>>(ga);
    }

    // fused output: passthrough or (d_x + Σ parts) * rw
    out_kernel<<<BSROWS, 256>>>(hs, out);
}

// round 12
// speedup vs baseline: 1.1420x; 1.0203x over previous
#include <cuda_runtime.h>
#include <cuda_bf16.h>
#include <math.h>
#include <stdint.h>

// ---------------- problem constants ----------------
#define B   2
#define S   2048
#define D   2048
#define HQ  16
#define HKV 8
#define HD  128
#define FF  8192
#define KCAP 256
#define BSROWS (B*S)          // 4096
#define RMAX 512
#define EPSF 1e-6f

// ---------------- device scratch ----------------
__device__ float d_rw[BSROWS];
__device__ float d_thresh[B];
__device__ int   d_selidx[BSROWS];
__device__ int   d_selcnt[B];
__device__ int   d_off[B+1];
__device__ int   d_rows[1];
__device__ int   d_row_b[RMAX];
__device__ int   d_row_p[RMAX];
__device__ int   d_selg[BSROWS];
__device__ float d_x   [(size_t)RMAX*D];
__device__ float d_q   [(size_t)RMAX*HQ*HD];
__device__ float d_k   [(size_t)RMAX*HKV*HD];
__device__ float d_v   [(size_t)RMAX*HKV*HD];
__device__ float d_gg  [(size_t)RMAX*FF];
__device__ float d_uu  [(size_t)RMAX*FF];
__device__ float d_part[(size_t)4*RMAX*D];

// compact split-bf16 [hi|lo] (2K per row) weights and activations
#define OFF_WQ 0
#define OFF_WK (OFF_WQ + (size_t)2048*2*D)
#define OFF_WV (OFF_WK + (size_t)1024*2*D)
#define OFF_WO (OFF_WV + (size_t)1024*2*D)
#define OFF_WG (OFF_WO + (size_t)2048*2*D)
#define OFF_WU (OFF_WG + (size_t)8192*2*D)
#define OFF_WD (OFF_WU + (size_t)8192*2*D)
#define W2_TOTAL (OFF_WD + (size_t)2048*2*FF)
__device__ __nv_bfloat16 d_w2[W2_TOTAL];
__device__ __nv_bfloat16 d_a2[(size_t)RMAX*2*FF];

// ---------------- helpers ----------------
__device__ __forceinline__ uint32_t smem_to_u32(const void* p) {
    uint32_t a;
    asm("{ .reg .u64 t; cvta.to.shared.u64 t, %1; cvt.u32.u64 %0, t; }" : "=r"(a) : "l"(p));
    return a;
}
__device__ __forceinline__ void cp_async16(uint32_t dst, const void* src, int sz) {
    asm volatile("cp.async.cg.shared.global [%0], [%1], 16, %2;"
                 :: "r"(dst), "l"(src), "r"(sz) : "memory");
}
__device__ __forceinline__ void cp_commit() { asm volatile("cp.async.commit_group;" ::: "memory"); }
__device__ __forceinline__ void cp_wait1()  { asm volatile("cp.async.wait_group 1;" ::: "memory"); }
__device__ __forceinline__ void ldsm4(uint32_t& r0, uint32_t& r1, uint32_t& r2, uint32_t& r3, uint32_t a) {
    asm volatile("ldmatrix.sync.aligned.m8n8.x4.shared.b16 {%0,%1,%2,%3}, [%4];"
                 : "=r"(r0), "=r"(r1), "=r"(r2), "=r"(r3) : "r"(a));
}
__device__ __forceinline__ void mma_bf16(float* c, const uint32_t* a, uint32_t b0, uint32_t b1) {
    asm volatile("mma.sync.aligned.m16n8k16.row.col.f32.bf16.bf16.f32 "
                 "{%0,%1,%2,%3}, {%4,%5,%6,%7}, {%8,%9}, {%0,%1,%2,%3};"
                 : "+f"(c[0]), "+f"(c[1]), "+f"(c[2]), "+f"(c[3])
                 : "r"(a[0]), "r"(a[1]), "r"(a[2]), "r"(a[3]), "r"(b0), "r"(b1));
}
__device__ __forceinline__ uint32_t pack_bf2(float a, float b) {
    __nv_bfloat162 t = __floats2bfloat162_rn(a, b);
    return *(uint32_t*)&t;
}
__device__ __forceinline__ void split4(float4 v, uint2& hi, uint2& lo) {
    float h0 = __bfloat162float(__float2bfloat16(v.x));
    float h1 = __bfloat162float(__float2bfloat16(v.y));
    float h2 = __bfloat162float(__float2bfloat16(v.z));
    float h3 = __bfloat162float(__float2bfloat16(v.w));
    hi = make_uint2(pack_bf2(h0,h1), pack_bf2(h2,h3));
    lo = make_uint2(pack_bf2(v.x-h0, v.y-h1), pack_bf2(v.z-h2, v.w-h3));
}

// ---------------- merged weight conversion (7 segments) ----------------
struct WSeg { const float* src; __nv_bfloat16* dst; int total; int kshift; int K; };
struct WAll { WSeg s[7]; };

__global__ void convert_all_kernel(WAll wa) {
    #pragma unroll 1
    for (int sgi = 0; sgi < 7; sgi++) {
        const float* __restrict__ src = wa.s[sgi].src;
        __nv_bfloat16* __restrict__ dst = wa.s[sgi].dst;
        int K = wa.s[sgi].K;
        int ks = wa.s[sgi].kshift;
        int total = wa.s[sgi].total;
        int kmask = (1 << ks) - 1;
        for (int idx = blockIdx.x * 256 + threadIdx.x; idx < total; idx += gridDim.x * 256) {
            int n = idx >> ks, c8 = (idx & kmask) << 3;
            const float* sp = src + (size_t)n * K + c8;
            float4 v0 = *(const float4*)(sp);
            float4 v1 = *(const float4*)(sp + 4);
            uint2 hiA, loA, hiB, loB;
            split4(v0, hiA, loA);
            split4(v1, hiB, loB);
            size_t b = (size_t)n * 2 * K + c8;
            *(uint4*)(dst + b)     = make_uint4(hiA.x, hiA.y, hiB.x, hiB.y);
            *(uint4*)(dst + b + K) = make_uint4(loA.x, loA.y, loB.x, loB.y);
        }
    }
}

// ---------------- tensor-core GEMM: 4 warps, 64x64 warp tiles (smem-traffic lever) ----------------
// Virtual K3 = 3K: vA(k)=k<2K?k:k-2K over A2=[hi|lo]; vW(k)=k<K?k:k-K over W2=[hi|lo].
// CTA tile 128x128, 128 threads (2x2 warps, 64x64 warp tile), BK=64, 3-stage cp.async.
struct Seg { const __nv_bfloat16* W2; const float* bias; float* C; int N; int ntiles; };
struct GArgs { const __nv_bfloat16* A2; int K; int kSplit; int nseg; Seg s[3]; };

#define STAGES 3
#define STAGE_BYTES 32768   // A 16KB + W 16KB (128 rows x 128 bytes each)
#define SM_TOTAL (STAGES*STAGE_BYTES)

__global__ void __launch_bounds__(128, 2) mma_gemm(GArgs ga) {
    extern __shared__ char smem[];
    uint32_t sb = smem_to_u32(smem);
    int tid = threadIdx.x;
    int rows = d_rows[0]; if (rows > RMAX) rows = RMAX;
    int m0 = blockIdx.y * 128;
    int Kp = ga.K;
    int K3 = 3 * Kp;

    Seg sg = ga.s[0];
    int nt = blockIdx.x;
    if (ga.nseg > 1 && nt >= ga.s[0].ntiles) {
        nt -= ga.s[0].ntiles; sg = ga.s[1];
        if (ga.nseg > 2 && nt >= ga.s[1].ntiles) { nt -= ga.s[1].ntiles; sg = ga.s[2]; }
    }
    int n0g = nt * 128;
    int kLen = K3 / ga.kSplit;
    int kOff = blockIdx.z * kLen;
    int iters = kLen / 64;

    const __nv_bfloat16* Abase = ga.A2;
    const __nv_bfloat16* Wbase = sg.W2 + (size_t)n0g * 2 * Kp;

    // loader: per stage A = 1024 16B-chunks (8/thread), W = 1024 (8/thread)
    int lrow[8], lch[8]; uint32_t lsw[8];
    #pragma unroll
    for (int q = 0; q < 8; q++) {
        int j = tid + q * 128;
        lrow[q] = j >> 3; lch[q] = j & 7;
        lsw[q] = lrow[q] * 128 + ((lch[q] ^ (lrow[q] & 7)) << 4);
    }

    #define LOAD_STAGE(stage, kElem) do { \
        int _aK = (kElem) < 2*Kp ? (kElem) : (kElem) - 2*Kp; \
        int _wK = (kElem) < Kp   ? (kElem) : (kElem) - Kp; \
        uint32_t sA = sb + (stage) * STAGE_BYTES; \
        uint32_t sW = sA + 16384; \
        _Pragma("unroll") \
        for (int q = 0; q < 8; q++) { \
            int gm = m0 + lrow[q]; \
            cp_async16(sA + lsw[q], Abase + (size_t)gm * 2 * Kp + _aK + lch[q]*8, gm < rows ? 16 : 0); \
            cp_async16(sW + lsw[q], Wbase + (size_t)lrow[q] * 2 * Kp + _wK + lch[q]*8, 16); \
        } \
    } while (0)

    LOAD_STAGE(0, kOff); cp_commit();
    LOAD_STAGE(1, kOff + 64); cp_commit();

    int lane = tid & 31, wid = tid >> 5;
    int wm = wid >> 1, wn = wid & 1;       // 2x2 warp grid, 64x64 tiles
    float acc[4][8][4];
    #pragma unroll
    for (int a = 0; a < 4; a++)
        #pragma unroll
        for (int b = 0; b < 8; b++)
            #pragma unroll
            for (int c = 0; c < 4; c++) acc[a][b][c] = 0.f;

    int arow_[4];
    #pragma unroll
    for (int mi = 0; mi < 4; mi++) arow_[mi] = wm * 64 + mi * 16 + (lane & 15);
    int ach_ = lane >> 4;
    int brow_[4];
    #pragma unroll
    for (int p = 0; p < 4; p++) brow_[p] = wn * 64 + p * 16 + (lane & 7) + ((lane >> 4) << 3);
    int bch_ = (lane >> 3) & 1;

    for (int i = 0; i < iters; i++) {
        cp_wait1();
        __syncthreads();
        int nf = i + STAGES - 1;
        if (nf < iters) LOAD_STAGE(nf % STAGES, kOff + nf * 64);
        cp_commit();

        uint32_t sA = sb + (i % STAGES) * STAGE_BYTES;
        uint32_t sW = sA + 16384;
        #pragma unroll
        for (int s2 = 0; s2 < 4; s2++) {
            uint32_t af[4][4];
            #pragma unroll
            for (int mi = 0; mi < 4; mi++) {
                int row = arow_[mi];
                int ch = 2 * s2 + ach_;
                uint32_t ad = sA + row * 128 + ((ch ^ (row & 7)) << 4);
                ldsm4(af[mi][0], af[mi][1], af[mi][2], af[mi][3], ad);
            }
            uint32_t b0[8], b1[8];
            #pragma unroll
            for (int p = 0; p < 4; p++) {
                int row = brow_[p];
                int ch = 2 * s2 + bch_;
                uint32_t bd = sW + row * 128 + ((ch ^ (row & 7)) << 4);
                uint32_t r0, r1, r2, r3;
                ldsm4(r0, r1, r2, r3, bd);
                b0[2*p] = r0; b1[2*p] = r1; b0[2*p+1] = r2; b1[2*p+1] = r3;
            }
            #pragma unroll
            for (int mi = 0; mi < 4; mi++)
                #pragma unroll
                for (int ni = 0; ni < 8; ni++)
                    mma_bf16(acc[mi][ni], af[mi], b0[ni], b1[ni]);
        }
        __syncthreads();
    }

    float* Cp = sg.C + (ga.kSplit > 1 ? (size_t)blockIdx.z * RMAX * sg.N : 0);
    int rr = lane >> 2;
    int cc = (lane & 3) * 2;
    #pragma unroll
    for (int mi = 0; mi < 4; mi++) {
        int m1 = m0 + wm * 64 + mi * 16 + rr;
        #pragma unroll
        for (int ni = 0; ni < 8; ni++) {
            int n1 = n0g + wn * 64 + ni * 8 + cc;
            float bx = 0.f, by = 0.f;
            if (sg.bias) { bx = sg.bias[n1]; by = sg.bias[n1 + 1]; }
            if (m1 < rows)
                *(float2*)(Cp + (size_t)m1 * sg.N + n1) =
                    make_float2(acc[mi][ni][0] + bx, acc[mi][ni][1] + by);
            if (m1 + 8 < rows)
                *(float2*)(Cp + (size_t)(m1 + 8) * sg.N + n1) =
                    make_float2(acc[mi][ni][2] + bx, acc[mi][ni][3] + by);
        }
    }
    #undef LOAD_STAGE
}

// ---------------- router / topk / select+map ----------------
__global__ void router_kernel(const float* __restrict__ hs, const float* __restrict__ rwv) {
    int row  = blockIdx.x * 8 + (threadIdx.x >> 5);
    int lane = threadIdx.x & 31;
    if (row >= BSROWS) return;
    const float* x = hs + (size_t)row * D;
    float s = 0.f;
    for (int i = lane; i < D; i += 32) s += x[i] * rwv[i];
    #pragma unroll
    for (int o = 16; o; o >>= 1) s += __shfl_xor_sync(0xffffffffu, s, o);
    if (lane == 0) d_rw[row] = s;
}

__global__ void topk_kernel() {
    __shared__ float s[S];
    int b = blockIdx.x;
    int t = threadIdx.x;
    s[t] = d_rw[b*S + t]; s[t + 1024] = d_rw[b*S + t + 1024];
    for (int k = 2; k <= S; k <<= 1)
        for (int j = k >> 1; j > 0; j >>= 1) {
            __syncthreads();
            for (int i = t; i < S; i += 1024) {
                int ixj = i ^ j;
                if (ixj > i) {
                    bool up = ((i & k) == 0);
                    float a = s[i], c = s[ixj];
                    if ((a > c) == up) { s[i] = c; s[ixj] = a; }
                }
            }
        }
    __syncthreads();
    if (t == 0) d_thresh[b] = s[S - KCAP];
}

__global__ void selmap_kernel() {
    int t = threadIdx.x;                      // 1024 threads
    for (int i = t; i < BSROWS; i += 1024) d_selg[i] = -1;
    int wid = t >> 5, lane = t & 31;
    if (wid < B) {
        int b = wid;
        float th = d_thresh[b];
        int total = 0;
        for (int c = 0; c < S/32; c++) {
            int idx = c*32 + lane;
            bool f = d_rw[b*S + idx] >= th;
            unsigned m = __ballot_sync(0xffffffffu, f);
            int pre = __popc(m & ((1u << lane) - 1u));
            if (f) d_selidx[b*S + total + pre] = idx;
            total += __popc(m);
        }
        if (lane == 0) d_selcnt[b] = total;
    }
    __syncthreads();
    int c0 = d_selcnt[0], c1 = d_selcnt[1];
    int rows = c0 + c1; if (rows > RMAX) rows = RMAX;
    if (t == 0) { d_off[0]=0; d_off[1]=c0; d_off[2]=c0+c1; d_rows[0]=rows; }
    for (int i = t; i < c0; i += 1024) if (i < RMAX) {
        int p = d_selidx[i];
        d_row_b[i] = 0; d_row_p[i] = p; d_selg[p] = i;
    }
    for (int i = t; i < c1; i += 1024) if (c0 + i < RMAX) {
        int p = d_selidx[S + i];
        d_row_b[c0+i] = 1; d_row_p[c0+i] = p; d_selg[S + p] = c0 + i;
    }
}

// ---------------- gather + rmsnorm -> a2 (and d_x) fused ----------------
__global__ void gather_rms_a2_kernel(const float* __restrict__ hs, const float* __restrict__ w) {
    int g = blockIdx.x;
    if (g >= d_rows[0]) return;
    int b = d_row_b[g], p = d_row_p[g];
    const float4* src = (const float4*)(hs + ((size_t)b*S + p) * D);
    float4* dx = (float4*)(d_x + (size_t)g * D);
    float ss = 0.f;
    for (int i = threadIdx.x; i < D/4; i += 256) {
        float4 v = src[i]; dx[i] = v;
        ss += v.x*v.x + v.y*v.y + v.z*v.z + v.w*v.w;
    }
    __shared__ float red[8];
    int lane = threadIdx.x & 31, wid = threadIdx.x >> 5;
    #pragma unroll
    for (int o = 16; o; o >>= 1) ss += __shfl_xor_sync(0xffffffffu, ss, o);
    if (lane == 0) red[wid] = ss;
    __syncthreads();
    if (threadIdx.x == 0) { float v=0.f; for (int i=0;i<8;i++) v+=red[i]; red[0]=v; }
    __syncthreads();
    float inv = rsqrtf(red[0] / (float)D + EPSF);
    __nv_bfloat16* drow = d_a2 + (size_t)g * 2 * D;
    const float4* wv4 = (const float4*)w;
    for (int i = threadIdx.x; i < D/4; i += 256) {
        float4 v = dx[i], ww = wv4[i];
        float4 hv = make_float4(v.x*inv*ww.x, v.y*inv*ww.y, v.z*inv*ww.z, v.w*inv*ww.w);
        uint2 hi, lo; split4(hv, hi, lo);
        *(uint2*)(drow + i*4)     = hi;
        *(uint2*)(drow + D + i*4) = lo;
    }
}

// ---------------- O-reduce(2) + residual + rmsnorm -> a2, updates d_x ----------------
__global__ void rms_reduce_a2_kernel(const float* __restrict__ w) {
    int g = blockIdx.x;
    if (g >= d_rows[0]) return;
    float4* dx = (float4*)(d_x + (size_t)g * D);
    const float4* p0 = (const float4*)(d_part + (size_t)g * D);
    const float4* p1 = (const float4*)(d_part + (size_t)RMAX * D + (size_t)g * D);
    float ss = 0.f;
    for (int i = threadIdx.x; i < D/4; i += 256) {
        float4 v = dx[i], a = p0[i], b = p1[i];
        v.x += a.x + b.x; v.y += a.y + b.y; v.z += a.z + b.z; v.w += a.w + b.w;
        dx[i] = v;
        ss += v.x*v.x + v.y*v.y + v.z*v.z + v.w*v.w;
    }
    __shared__ float red[8];
    int lane = threadIdx.x & 31, wid = threadIdx.x >> 5;
    #pragma unroll
    for (int o = 16; o; o >>= 1) ss += __shfl_xor_sync(0xffffffffu, ss, o);
    if (lane == 0) red[wid] = ss;
    __syncthreads();
    if (threadIdx.x == 0) { float v=0.f; for (int i=0;i<8;i++) v+=red[i]; red[0]=v; }
    __syncthreads();
    float inv = rsqrtf(red[0] / (float)D + EPSF);
    __nv_bfloat16* drow = d_a2 + (size_t)g * 2 * D;
    const float4* wv4 = (const float4*)w;
    for (int i = threadIdx.x; i < D/4; i += 256) {
        float4 v = dx[i], ww = wv4[i];
        float4 hv = make_float4(v.x*inv*ww.x, v.y*inv*ww.y, v.z*inv*ww.z, v.w*inv*ww.w);
        uint2 hi, lo; split4(hv, hi, lo);
        *(uint2*)(drow + i*4)     = hi;
        *(uint2*)(drow + D + i*4) = lo;
    }
}

// ---------------- RoPE ----------------
__global__ void rope_kernel() {
    int g = blockIdx.x;
    if (g >= d_rows[0]) return;
    float fp = (float)d_row_p[g];
    const float L2_10000 = 13.287712379549449f;
    for (int idx = threadIdx.x; idx < (HQ + HKV) * 64; idx += 256) {
        int head = idx >> 6;
        int i = idx & 63;
        float inv = exp2f(-(float)i * (L2_10000 / 64.0f));
        float fr = fp * inv;
        float c = cosf(fr), s = sinf(fr);
        float* ptr;
        if (head < HQ) ptr = d_q + (size_t)g*(HQ*HD) + head*HD;
        else           ptr = d_k + (size_t)g*(HKV*HD) + (head-HQ)*HD;
        float x1 = ptr[i], x2 = ptr[i+64];
        ptr[i]    = x1*c - x2*s;
        ptr[i+64] = x2*c + x1*s;
    }
}

// ---------------- attention -> a2 directly ----------------
__global__ void attn_kernel() {
    int g = blockIdx.x;
    if (g >= d_rows[0]) return;
    int h = threadIdx.y + blockIdx.y * 8;
    int b = d_row_b[g];
    int off = d_off[b];
    int r = g - off;
    int p = d_row_p[g];
    int lane = threadIdx.x;
    int kvh = h >> 1;

    float4 qv = *(const float4*)(d_q + (size_t)g*(HQ*HD) + h*HD + lane*4);
    const float scale = 0.08838834764831843f;

    float m = -INFINITY, l = 0.f;
    float4 acc = make_float4(0.f, 0.f, 0.f, 0.f);

    for (int j = 0; j <= r; j++) {
        const float* kp = d_k + (size_t)(off + j)*(HKV*HD) + kvh*HD;
        float4 kv = *(const float4*)(kp + lane*4);
        float sdot = qv.x*kv.x + qv.y*kv.y + qv.z*kv.z + qv.w*kv.w;
        #pragma unroll
        for (int o = 16; o; o >>= 1) sdot += __shfl_xor_sync(0xffffffffu, sdot, o);
        float sc = sdot * scale;
        float mn = fmaxf(m, sc);
        float eo = expf(m - mn);
        float ec = expf(sc - mn);
        const float* vp = d_v + (size_t)(off + j)*(HKV*HD) + kvh*HD;
        float4 vv = *(const float4*)(vp + lane*4);
        l = l*eo + ec;
        acc.x = acc.x*eo + ec*vv.x;
        acc.y = acc.y*eo + ec*vv.y;
        acc.z = acc.z*eo + ec*vv.z;
        acc.w = acc.w*eo + ec*vv.w;
        m = mn;
    }
    int zc = p - r;
    if (zc > 0) {
        float mn = fmaxf(m, 0.f);
        float eo = expf(m - mn);
        l = l*eo + (float)zc * expf(-mn);
        acc.x *= eo; acc.y *= eo; acc.z *= eo; acc.w *= eo;
    }
    float invl = 1.f / l;
    float4 o4 = make_float4(acc.x*invl, acc.y*invl, acc.z*invl, acc.w*invl);
    uint2 hi, lo; split4(o4, hi, lo);
    __nv_bfloat16* drow = d_a2 + (size_t)g * 2 * D + h * HD + lane * 4;
    *(uint2*)(drow)     = hi;
    *(uint2*)(drow + D) = lo;
}

// ---------------- silu(g)*u -> a2 (K=FF) ----------------
__global__ void silu_a2_kernel() {
    int g = blockIdx.x;
    if (g >= d_rows[0]) return;
    const float4* gr = (const float4*)(d_gg + (size_t)g * FF);
    const float4* ur = (const float4*)(d_uu + (size_t)g * FF);
    __nv_bfloat16* drow = d_a2 + (size_t)g * 2 * FF;
    for (int i = threadIdx.x; i < FF/4; i += 256) {
        float4 x = gr[i], u = ur[i];
        float4 s;
        s.x = (x.x / (1.f + expf(-x.x))) * u.x;
        s.y = (x.y / (1.f + expf(-x.y))) * u.y;
        s.z = (x.z / (1.f + expf(-x.z))) * u.z;
        s.w = (x.w / (1.f + expf(-x.w))) * u.w;
        uint2 hi, lo; split4(s, hi, lo);
        *(uint2*)(drow + i*4)      = hi;
        *(uint2*)(drow + FF + i*4) = lo;
    }
}

// ---------------- fused output: passthrough OR (residual + down-reduce(4)) * rw ----------------
__global__ void out_kernel(const float* __restrict__ hs, float* __restrict__ out) {
    int r = blockIdx.x;
    int g = d_selg[r];
    const float4* src = (const float4*)(hs + (size_t)r * D);
    float4* dst = (float4*)(out + (size_t)r * D);
    if (g < 0) {
        for (int i = threadIdx.x; i < D/4; i += 256) dst[i] = src[i];
    } else {
        float sc = d_rw[r];
        const float4* xs = (const float4*)(d_x + (size_t)g * D);
        const float4* p0 = (const float4*)(d_part + (size_t)g * D);
        const float4* p1 = (const float4*)(d_part + (size_t)RMAX * D + (size_t)g * D);
        const float4* p2 = (const float4*)(d_part + (size_t)2 * RMAX * D + (size_t)g * D);
        const float4* p3 = (const float4*)(d_part + (size_t)3 * RMAX * D + (size_t)g * D);
        for (int i = threadIdx.x; i < D/4; i += 256) {
            float4 v = xs[i], a = p0[i], b = p1[i], c = p2[i], d = p3[i];
            v.x = (v.x + a.x + b.x + c.x + d.x) * sc;
            v.y = (v.y + a.y + b.y + c.y + d.y) * sc;
            v.z = (v.z + a.z + b.z + c.z + d.z) * sc;
            v.w = (v.w + a.w + b.w + c.w + d.w) * sc;
            dst[i] = v;
        }
    }
}

// ---------------- launch ----------------
extern "C" void kernel_launch(void* const* d_in, const int* in_sizes, int n_in,
                              void* d_out, int out_size) {
    const float* hs    = (const float*)d_in[0];
    const float* rwv   = (const float*)d_in[1];
    const float* wq    = (const float*)d_in[2];
    const float* bq    = (const float*)d_in[3];
    const float* wk    = (const float*)d_in[4];
    const float* bk    = (const float*)d_in[5];
    const float* wv    = (const float*)d_in[6];
    const float* bv    = (const float*)d_in[7];
    const float* wo    = (const float*)d_in[8];
    const float* wgate = (const float*)d_in[9];
    const float* wup   = (const float*)d_in[10];
    const float* wdown = (const float*)d_in[11];
    const float* ln1w  = (const float*)d_in[12];
    const float* ln2w  = (const float*)d_in[13];
    float* out = (float*)d_out;

    float *px, *pq, *pk, *pv, *pg, *pu, *ppart;
    __nv_bfloat16 *pw2, *pa2;
    cudaGetSymbolAddress((void**)&px,    d_x);
    cudaGetSymbolAddress((void**)&pq,    d_q);
    cudaGetSymbolAddress((void**)&pk,    d_k);
    cudaGetSymbolAddress((void**)&pv,    d_v);
    cudaGetSymbolAddress((void**)&pg,    d_gg);
    cudaGetSymbolAddress((void**)&pu,    d_uu);
    cudaGetSymbolAddress((void**)&pw2,   d_w2);
    cudaGetSymbolAddress((void**)&pa2,   d_a2);
    cudaGetSymbolAddress((void**)&ppart, d_part);

    static int attr_done = 0;
    if (!attr_done) {
        cudaFuncSetAttribute(mma_gemm, cudaFuncAttributeMaxDynamicSharedMemorySize, SM_TOTAL);
        attr_done = 1;
    }

    router_kernel<<<BSROWS/8, 256>>>(hs, rwv);
    topk_kernel<<<B, 1024>>>();
    selmap_kernel<<<1, 1024>>>();
    gather_rms_a2_kernel<<<RMAX, 256>>>(hs, ln1w);

    // all weight conversions in one launch
    {
        WAll wa;
        wa.s[0] = { wq,    pw2 + OFF_WQ, 2048*(D/8),  8,  D };
        wa.s[1] = { wk,    pw2 + OFF_WK, 1024*(D/8),  8,  D };
        wa.s[2] = { wv,    pw2 + OFF_WV, 1024*(D/8),  8,  D };
        wa.s[3] = { wo,    pw2 + OFF_WO, 2048*(D/8),  8,  D };
        wa.s[4] = { wgate, pw2 + OFF_WG, 8192*(D/8),  8,  D };
        wa.s[5] = { wup,   pw2 + OFF_WU, 8192*(D/8),  8,  D };
        wa.s[6] = { wdown, pw2 + OFF_WD, 2048*(FF/8), 10, FF };
        convert_all_kernel<<<2368, 256>>>(wa);
    }

    // QKV GEMM
    {
        GArgs ga = {};
        ga.A2 = pa2; ga.K = D; ga.kSplit = 1; ga.nseg = 3;
        ga.s[0] = { pw2 + OFF_WQ, bq, pq, HQ*HD,  16 };
        ga.s[1] = { pw2 + OFF_WK, bk, pk, HKV*HD, 8  };
        ga.s[2] = { pw2 + OFF_WV, bv, pv, HKV*HD, 8  };
        mma_gemm<<<dim3(32, 4, 1), 128, SM_TOTAL>>>(ga);
    }
    rope_kernel<<<RMAX, 256>>>();
    attn_kernel<<<dim3(RMAX, HQ/8), dim3(32, 8)>>>();
    // O projection, split-K 2 -> partials
    {
        GArgs ga = {};
        ga.A2 = pa2; ga.K = D; ga.kSplit = 2; ga.nseg = 1;
        ga.s[0] = { pw2 + OFF_WO, nullptr, ppart, D, 16 };
        mma_gemm<<<dim3(16, 4, 2), 128, SM_TOTAL>>>(ga);
    }
    // fused: reduce(2) + residual + rmsnorm2 -> a2 (updates d_x)
    rms_reduce_a2_kernel<<<RMAX, 256>>>(ln2w);
    // gate + up merged
    {
        GArgs ga = {};
        ga.A2 = pa2; ga.K = D; ga.kSplit = 1; ga.nseg = 2;
        ga.s[0] = { pw2 + OFF_WG, nullptr, pg, FF, 64 };
        ga.s[1] = { pw2 + OFF_WU, nullptr, pu, FF, 64 };
        mma_gemm<<<dim3(128, 4, 1), 128, SM_TOTAL>>>(ga);
    }
    silu_a2_kernel<<<RMAX, 256>>>();
    // down, split-K 4 -> partials (reduced in out_kernel)
    {
        GArgs ga = {};
        ga.A2 = pa2; ga.K = FF; ga.kSplit = 4; ga.nseg = 1;
        ga.s[0] = { pw2 + OFF_WD, nullptr, ppart, D, 16 };
        mma_gemm<<<dim3(16, 4, 4), 128, SM_TOTAL>>>(ga);
    }

    // fused output: passthrough or (d_x + Σ parts) * rw
    out_kernel<<<BSROWS, 256>>>(hs, out);
}

// round 13
// speedup vs baseline: 1.5033x; 1.3163x over previous
#include <cuda_runtime.h>
#include <cuda_bf16.h>
#include <cuda_fp16.h>
#include <math.h>
#include <stdint.h>

// ---------------- problem constants ----------------
#define B   2
#define S   2048
#define D   2048
#define HQ  16
#define HKV 8
#define HD  128
#define FF  8192
#define KCAP 256
#define BSROWS (B*S)          // 4096
#define RMAX 512
#define EPSF 1e-6f

// ---------------- device scratch ----------------
__device__ float d_rw[BSROWS];
__device__ float d_thresh[B];
__device__ int   d_selidx[BSROWS];
__device__ int   d_selcnt[B];
__device__ int   d_off[B+1];
__device__ int   d_rows[1];
__device__ int   d_row_b[RMAX];
__device__ int   d_row_p[RMAX];
__device__ int   d_selg[BSROWS];
__device__ float d_x   [(size_t)RMAX*D];
__device__ float d_q   [(size_t)RMAX*HQ*HD];
__device__ float d_k   [(size_t)RMAX*HKV*HD];
__device__ float d_v   [(size_t)RMAX*HKV*HD];
__device__ float d_gg  [(size_t)RMAX*FF];
__device__ float d_uu  [(size_t)RMAX*FF];
__device__ float d_part[(size_t)4*RMAX*D];

// fp16 weights (hi only, K per row) and activations (split-2 [hi|lo], 2K per row)
#define OFF_WQ 0
#define OFF_WK (OFF_WQ + (size_t)2048*D)
#define OFF_WV (OFF_WK + (size_t)1024*D)
#define OFF_WO (OFF_WV + (size_t)1024*D)
#define OFF_WG (OFF_WO + (size_t)2048*D)
#define OFF_WU (OFF_WG + (size_t)8192*D)
#define OFF_WD (OFF_WU + (size_t)8192*D)
#define W2_TOTAL (OFF_WD + (size_t)2048*FF)
__device__ __half d_w2[W2_TOTAL];
__device__ __half d_a2[(size_t)RMAX*2*FF];

// ---------------- helpers ----------------
__device__ __forceinline__ uint32_t smem_to_u32(const void* p) {
    uint32_t a;
    asm("{ .reg .u64 t; cvta.to.shared.u64 t, %1; cvt.u32.u64 %0, t; }" : "=r"(a) : "l"(p));
    return a;
}
__device__ __forceinline__ void cp_async16(uint32_t dst, const void* src, int sz) {
    asm volatile("cp.async.cg.shared.global [%0], [%1], 16, %2;"
                 :: "r"(dst), "l"(src), "r"(sz) : "memory");
}
__device__ __forceinline__ void cp_commit() { asm volatile("cp.async.commit_group;" ::: "memory"); }
__device__ __forceinline__ void cp_wait1()  { asm volatile("cp.async.wait_group 1;" ::: "memory"); }
__device__ __forceinline__ void ldsm4(uint32_t& r0, uint32_t& r1, uint32_t& r2, uint32_t& r3, uint32_t a) {
    asm volatile("ldmatrix.sync.aligned.m8n8.x4.shared.b16 {%0,%1,%2,%3}, [%4];"
                 : "=r"(r0), "=r"(r1), "=r"(r2), "=r"(r3) : "r"(a));
}
__device__ __forceinline__ void mma_f16(float* c, const uint32_t* a, uint32_t b0, uint32_t b1) {
    asm volatile("mma.sync.aligned.m16n8k16.row.col.f32.f16.f16.f32 "
                 "{%0,%1,%2,%3}, {%4,%5,%6,%7}, {%8,%9}, {%0,%1,%2,%3};"
                 : "+f"(c[0]), "+f"(c[1]), "+f"(c[2]), "+f"(c[3])
                 : "r"(a[0]), "r"(a[1]), "r"(a[2]), "r"(a[3]), "r"(b0), "r"(b1));
}
// split one fp32x4 into fp16 hi/lo pairs (activation: exact 2-term representation)
__device__ __forceinline__ void split4h(float4 v, uint2& hi, uint2& lo) {
    __half2 h01 = __floats2half2_rn(v.x, v.y);
    __half2 h23 = __floats2half2_rn(v.z, v.w);
    float2 f01 = __half22float2(h01), f23 = __half22float2(h23);
    __half2 l01 = __floats2half2_rn(v.x - f01.x, v.y - f01.y);
    __half2 l23 = __floats2half2_rn(v.z - f23.x, v.w - f23.y);
    hi = make_uint2(*(uint32_t*)&h01, *(uint32_t*)&h23);
    lo = make_uint2(*(uint32_t*)&l01, *(uint32_t*)&l23);
}

// ---------------- merged weight conversion: W f32 -> fp16 hi only ----------------
struct WSeg { const float* src; __half* dst; int total; };
struct WAll { WSeg s[7]; };

__global__ void convert_all_kernel(WAll wa) {
    #pragma unroll 1
    for (int sgi = 0; sgi < 7; sgi++) {
        const float* __restrict__ src = wa.s[sgi].src;
        __half* __restrict__ dst = wa.s[sgi].dst;
        int total = wa.s[sgi].total;       // N*K/8
        for (int idx = blockIdx.x * 256 + threadIdx.x; idx < total; idx += gridDim.x * 256) {
            size_t c8 = (size_t)idx << 3;
            const float* sp = src + c8;
            float4 v0 = *(const float4*)(sp);
            float4 v1 = *(const float4*)(sp + 4);
            __half2 h01 = __floats2half2_rn(v0.x, v0.y);
            __half2 h23 = __floats2half2_rn(v0.z, v0.w);
            __half2 h45 = __floats2half2_rn(v1.x, v1.y);
            __half2 h67 = __floats2half2_rn(v1.z, v1.w);
            *(uint4*)(dst + c8) = make_uint4(*(uint32_t*)&h01, *(uint32_t*)&h23,
                                             *(uint32_t*)&h45, *(uint32_t*)&h67);
        }
    }
}

// ---------------- tensor-core GEMM (fp16 split-2 via virtual K remap) ----------------
// Virtual K2 = 2K: vA(k)=k over A2=[hi|lo]; vW(k)=k<K?k:k-K over W (hi only).
// -> terms hiA.hiW + loA.hiW. Activation split exact; error = weight fp16 rounding (~3e-4).
// CTA tile 128x128, 128 threads (2x2 warps, 64x64 warp tile), BK=64, 3-stage cp.async.
struct Seg { const __half* W2; const float* bias; float* C; int N; int ntiles; };
struct GArgs { const __half* A2; int K; int kSplit; int nseg; Seg s[3]; };

#define STAGES 3
#define STAGE_BYTES 32768   // A 16KB + W 16KB (128 rows x 128 bytes each)
#define SM_TOTAL (STAGES*STAGE_BYTES)

__global__ void __launch_bounds__(128, 2) mma_gemm(GArgs ga) {
    extern __shared__ char smem[];
    uint32_t sb = smem_to_u32(smem);
    int tid = threadIdx.x;
    int rows = d_rows[0]; if (rows > RMAX) rows = RMAX;
    int m0 = blockIdx.y * 128;
    int Kp = ga.K;
    int K2 = 2 * Kp;

    Seg sg = ga.s[0];
    int nt = blockIdx.x;
    if (ga.nseg > 1 && nt >= ga.s[0].ntiles) {
        nt -= ga.s[0].ntiles; sg = ga.s[1];
        if (ga.nseg > 2 && nt >= ga.s[1].ntiles) { nt -= ga.s[1].ntiles; sg = ga.s[2]; }
    }
    int n0g = nt * 128;
    int kLen = K2 / ga.kSplit;
    int kOff = blockIdx.z * kLen;
    int iters = kLen / 64;

    const __half* Abase = ga.A2;
    const __half* Wbase = sg.W2 + (size_t)n0g * Kp;

    // loader: per stage A = 1024 16B-chunks (8/thread), W = 1024 (8/thread)
    int lrow[8], lch[8]; uint32_t lsw[8];
    #pragma unroll
    for (int q = 0; q < 8; q++) {
        int j = tid + q * 128;
        lrow[q] = j >> 3; lch[q] = j & 7;
        lsw[q] = lrow[q] * 128 + ((lch[q] ^ (lrow[q] & 7)) << 4);
    }

    #define LOAD_STAGE(stage, kElem) do { \
        int _aK = (kElem); \
        int _wK = (kElem) < Kp ? (kElem) : (kElem) - Kp; \
        uint32_t sA = sb + (stage) * STAGE_BYTES; \
        uint32_t sW = sA + 16384; \
        _Pragma("unroll") \
        for (int q = 0; q < 8; q++) { \
            int gm = m0 + lrow[q]; \
            cp_async16(sA + lsw[q], Abase + (size_t)gm * 2 * Kp + _aK + lch[q]*8, gm < rows ? 16 : 0); \
            cp_async16(sW + lsw[q], Wbase + (size_t)lrow[q] * Kp + _wK + lch[q]*8, 16); \
        } \
    } while (0)

    LOAD_STAGE(0, kOff); cp_commit();
    LOAD_STAGE(1, kOff + 64); cp_commit();

    int lane = tid & 31, wid = tid >> 5;
    int wm = wid >> 1, wn = wid & 1;       // 2x2 warp grid, 64x64 tiles
    float acc[4][8][4];
    #pragma unroll
    for (int a = 0; a < 4; a++)
        #pragma unroll
        for (int b = 0; b < 8; b++)
            #pragma unroll
            for (int c = 0; c < 4; c++) acc[a][b][c] = 0.f;

    int arow_[4];
    #pragma unroll
    for (int mi = 0; mi < 4; mi++) arow_[mi] = wm * 64 + mi * 16 + (lane & 15);
    int ach_ = lane >> 4;
    int brow_[4];
    #pragma unroll
    for (int p = 0; p < 4; p++) brow_[p] = wn * 64 + p * 16 + (lane & 7) + ((lane >> 4) << 3);
    int bch_ = (lane >> 3) & 1;

    for (int i = 0; i < iters; i++) {
        cp_wait1();
        __syncthreads();
        int nf = i + STAGES - 1;
        if (nf < iters) LOAD_STAGE(nf % STAGES, kOff + nf * 64);
        cp_commit();

        uint32_t sA = sb + (i % STAGES) * STAGE_BYTES;
        uint32_t sW = sA + 16384;
        #pragma unroll
        for (int s2 = 0; s2 < 4; s2++) {
            uint32_t af[4][4];
            #pragma unroll
            for (int mi = 0; mi < 4; mi++) {
                int row = arow_[mi];
                int ch = 2 * s2 + ach_;
                uint32_t ad = sA + row * 128 + ((ch ^ (row & 7)) << 4);
                ldsm4(af[mi][0], af[mi][1], af[mi][2], af[mi][3], ad);
            }
            uint32_t b0[8], b1[8];
            #pragma unroll
            for (int p = 0; p < 4; p++) {
                int row = brow_[p];
                int ch = 2 * s2 + bch_;
                uint32_t bd = sW + row * 128 + ((ch ^ (row & 7)) << 4);
                uint32_t r0, r1, r2, r3;
                ldsm4(r0, r1, r2, r3, bd);
                b0[2*p] = r0; b1[2*p] = r1; b0[2*p+1] = r2; b1[2*p+1] = r3;
            }
            #pragma unroll
            for (int mi = 0; mi < 4; mi++)
                #pragma unroll
                for (int ni = 0; ni < 8; ni++)
                    mma_f16(acc[mi][ni], af[mi], b0[ni], b1[ni]);
        }
        __syncthreads();
    }

    float* Cp = sg.C + (ga.kSplit > 1 ? (size_t)blockIdx.z * RMAX * sg.N : 0);
    int rr = lane >> 2;
    int cc = (lane & 3) * 2;
    #pragma unroll
    for (int mi = 0; mi < 4; mi++) {
        int m1 = m0 + wm * 64 + mi * 16 + rr;
        #pragma unroll
        for (int ni = 0; ni < 8; ni++) {
            int n1 = n0g + wn * 64 + ni * 8 + cc;
            float bx = 0.f, by = 0.f;
            if (sg.bias) { bx = sg.bias[n1]; by = sg.bias[n1 + 1]; }
            if (m1 < rows)
                *(float2*)(Cp + (size_t)m1 * sg.N + n1) =
                    make_float2(acc[mi][ni][0] + bx, acc[mi][ni][1] + by);
            if (m1 + 8 < rows)
                *(float2*)(Cp + (size_t)(m1 + 8) * sg.N + n1) =
                    make_float2(acc[mi][ni][2] + bx, acc[mi][ni][3] + by);
        }
    }
    #undef LOAD_STAGE
}

// ---------------- router / topk / select+map ----------------
__global__ void router_kernel(const float* __restrict__ hs, const float* __restrict__ rwv) {
    int row  = blockIdx.x * 8 + (threadIdx.x >> 5);
    int lane = threadIdx.x & 31;
    if (row >= BSROWS) return;
    const float* x = hs + (size_t)row * D;
    float s = 0.f;
    for (int i = lane; i < D; i += 32) s += x[i] * rwv[i];
    #pragma unroll
    for (int o = 16; o; o >>= 1) s += __shfl_xor_sync(0xffffffffu, s, o);
    if (lane == 0) d_rw[row] = s;
}

__global__ void topk_kernel() {
    __shared__ float s[S];
    int b = blockIdx.x;
    int t = threadIdx.x;
    s[t] = d_rw[b*S + t]; s[t + 1024] = d_rw[b*S + t + 1024];
    for (int k = 2; k <= S; k <<= 1)
        for (int j = k >> 1; j > 0; j >>= 1) {
            __syncthreads();
            for (int i = t; i < S; i += 1024) {
                int ixj = i ^ j;
                if (ixj > i) {
                    bool up = ((i & k) == 0);
                    float a = s[i], c = s[ixj];
                    if ((a > c) == up) { s[i] = c; s[ixj] = a; }
                }
            }
        }
    __syncthreads();
    if (t == 0) d_thresh[b] = s[S - KCAP];
}

__global__ void selmap_kernel() {
    int t = threadIdx.x;                      // 1024 threads
    for (int i = t; i < BSROWS; i += 1024) d_selg[i] = -1;
    int wid = t >> 5, lane = t & 31;
    if (wid < B) {
        int b = wid;
        float th = d_thresh[b];
        int total = 0;
        for (int c = 0; c < S/32; c++) {
            int idx = c*32 + lane;
            bool f = d_rw[b*S + idx] >= th;
            unsigned m = __ballot_sync(0xffffffffu, f);
            int pre = __popc(m & ((1u << lane) - 1u));
            if (f) d_selidx[b*S + total + pre] = idx;
            total += __popc(m);
        }
        if (lane == 0) d_selcnt[b] = total;
    }
    __syncthreads();
    int c0 = d_selcnt[0], c1 = d_selcnt[1];
    int rows = c0 + c1; if (rows > RMAX) rows = RMAX;
    if (t == 0) { d_off[0]=0; d_off[1]=c0; d_off[2]=c0+c1; d_rows[0]=rows; }
    for (int i = t; i < c0; i += 1024) if (i < RMAX) {
        int p = d_selidx[i];
        d_row_b[i] = 0; d_row_p[i] = p; d_selg[p] = i;
    }
    for (int i = t; i < c1; i += 1024) if (c0 + i < RMAX) {
        int p = d_selidx[S + i];
        d_row_b[c0+i] = 1; d_row_p[c0+i] = p; d_selg[S + p] = c0 + i;
    }
}

// ---------------- gather + rmsnorm -> a2 (and d_x) fused ----------------
__global__ void gather_rms_a2_kernel(const float* __restrict__ hs, const float* __restrict__ w) {
    int g = blockIdx.x;
    if (g >= d_rows[0]) return;
    int b = d_row_b[g], p = d_row_p[g];
    const float4* src = (const float4*)(hs + ((size_t)b*S + p) * D);
    float4* dx = (float4*)(d_x + (size_t)g * D);
    float ss = 0.f;
    for (int i = threadIdx.x; i < D/4; i += 256) {
        float4 v = src[i]; dx[i] = v;
        ss += v.x*v.x + v.y*v.y + v.z*v.z + v.w*v.w;
    }
    __shared__ float red[8];
    int lane = threadIdx.x & 31, wid = threadIdx.x >> 5;
    #pragma unroll
    for (int o = 16; o; o >>= 1) ss += __shfl_xor_sync(0xffffffffu, ss, o);
    if (lane == 0) red[wid] = ss;
    __syncthreads();
    if (threadIdx.x == 0) { float v=0.f; for (int i=0;i<8;i++) v+=red[i]; red[0]=v; }
    __syncthreads();
    float inv = rsqrtf(red[0] / (float)D + EPSF);
    __half* drow = d_a2 + (size_t)g * 2 * D;
    const float4* wv4 = (const float4*)w;
    for (int i = threadIdx.x; i < D/4; i += 256) {
        float4 v = dx[i], ww = wv4[i];
        float4 hv = make_float4(v.x*inv*ww.x, v.y*inv*ww.y, v.z*inv*ww.z, v.w*inv*ww.w);
        uint2 hi, lo; split4h(hv, hi, lo);
        *(uint2*)(drow + i*4)     = hi;
        *(uint2*)(drow + D + i*4) = lo;
    }
}

// ---------------- O-reduce(2) + residual + rmsnorm -> a2, updates d_x ----------------
__global__ void rms_reduce_a2_kernel(const float* __restrict__ w) {
    int g = blockIdx.x;
    if (g >= d_rows[0]) return;
    float4* dx = (float4*)(d_x + (size_t)g * D);
    const float4* p0 = (const float4*)(d_part + (size_t)g * D);
    const float4* p1 = (const float4*)(d_part + (size_t)RMAX * D + (size_t)g * D);
    float ss = 0.f;
    for (int i = threadIdx.x; i < D/4; i += 256) {
        float4 v = dx[i], a = p0[i], b = p1[i];
        v.x += a.x + b.x; v.y += a.y + b.y; v.z += a.z + b.z; v.w += a.w + b.w;
        dx[i] = v;
        ss += v.x*v.x + v.y*v.y + v.z*v.z + v.w*v.w;
    }
    __shared__ float red[8];
    int lane = threadIdx.x & 31, wid = threadIdx.x >> 5;
    #pragma unroll
    for (int o = 16; o; o >>= 1) ss += __shfl_xor_sync(0xffffffffu, ss, o);
    if (lane == 0) red[wid] = ss;
    __syncthreads();
    if (threadIdx.x == 0) { float v=0.f; for (int i=0;i<8;i++) v+=red[i]; red[0]=v; }
    __syncthreads();
    float inv = rsqrtf(red[0] / (float)D + EPSF);
    __half* drow = d_a2 + (size_t)g * 2 * D;
    const float4* wv4 = (const float4*)w;
    for (int i = threadIdx.x; i < D/4; i += 256) {
        float4 v = dx[i], ww = wv4[i];
        float4 hv = make_float4(v.x*inv*ww.x, v.y*inv*ww.y, v.z*inv*ww.z, v.w*inv*ww.w);
        uint2 hi, lo; split4h(hv, hi, lo);
        *(uint2*)(drow + i*4)     = hi;
        *(uint2*)(drow + D + i*4) = lo;
    }
}

// ---------------- RoPE ----------------
__global__ void rope_kernel() {
    int g = blockIdx.x;
    if (g >= d_rows[0]) return;
    float fp = (float)d_row_p[g];
    const float L2_10000 = 13.287712379549449f;
    for (int idx = threadIdx.x; idx < (HQ + HKV) * 64; idx += 256) {
        int head = idx >> 6;
        int i = idx & 63;
        float inv = exp2f(-(float)i * (L2_10000 / 64.0f));
        float fr = fp * inv;
        float c = cosf(fr), s = sinf(fr);
        float* ptr;
        if (head < HQ) ptr = d_q + (size_t)g*(HQ*HD) + head*HD;
        else           ptr = d_k + (size_t)g*(HKV*HD) + (head-HQ)*HD;
        float x1 = ptr[i], x2 = ptr[i+64];
        ptr[i]    = x1*c - x2*s;
        ptr[i+64] = x2*c + x1*s;
    }
}

// ---------------- attention -> a2 directly ----------------
__global__ void attn_kernel() {
    int g = blockIdx.x;
    if (g >= d_rows[0]) return;
    int h = threadIdx.y + blockIdx.y * 8;
    int b = d_row_b[g];
    int off = d_off[b];
    int r = g - off;
    int p = d_row_p[g];
    int lane = threadIdx.x;
    int kvh = h >> 1;

    float4 qv = *(const float4*)(d_q + (size_t)g*(HQ*HD) + h*HD + lane*4);
    const float scale = 0.08838834764831843f;

    float m = -INFINITY, l = 0.f;
    float4 acc = make_float4(0.f, 0.f, 0.f, 0.f);

    for (int j = 0; j <= r; j++) {
        const float* kp = d_k + (size_t)(off + j)*(HKV*HD) + kvh*HD;
        float4 kv = *(const float4*)(kp + lane*4);
        float sdot = qv.x*kv.x + qv.y*kv.y + qv.z*kv.z + qv.w*kv.w;
        #pragma unroll
        for (int o = 16; o; o >>= 1) sdot += __shfl_xor_sync(0xffffffffu, sdot, o);
        float sc = sdot * scale;
        float mn = fmaxf(m, sc);
        float eo = expf(m - mn);
        float ec = expf(sc - mn);
        const float* vp = d_v + (size_t)(off + j)*(HKV*HD) + kvh*HD;
        float4 vv = *(const float4*)(vp + lane*4);
        l = l*eo + ec;
        acc.x = acc.x*eo + ec*vv.x;
        acc.y = acc.y*eo + ec*vv.y;
        acc.z = acc.z*eo + ec*vv.z;
        acc.w = acc.w*eo + ec*vv.w;
        m = mn;
    }
    int zc = p - r;
    if (zc > 0) {
        float mn = fmaxf(m, 0.f);
        float eo = expf(m - mn);
        l = l*eo + (float)zc * expf(-mn);
        acc.x *= eo; acc.y *= eo; acc.z *= eo; acc.w *= eo;
    }
    float invl = 1.f / l;
    float4 o4 = make_float4(acc.x*invl, acc.y*invl, acc.z*invl, acc.w*invl);
    uint2 hi, lo; split4h(o4, hi, lo);
    __half* drow = d_a2 + (size_t)g * 2 * D + h * HD + lane * 4;
    *(uint2*)(drow)     = hi;
    *(uint2*)(drow + D) = lo;
}

// ---------------- silu(g)*u -> a2 (K=FF) ----------------
__global__ void silu_a2_kernel() {
    int g = blockIdx.x;
    if (g >= d_rows[0]) return;
    const float4* gr = (const float4*)(d_gg + (size_t)g * FF);
    const float4* ur = (const float4*)(d_uu + (size_t)g * FF);
    __half* drow = d_a2 + (size_t)g * 2 * FF;
    for (int i = threadIdx.x; i < FF/4; i += 256) {
        float4 x = gr[i], u = ur[i];
        float4 s;
        s.x = (x.x / (1.f + expf(-x.x))) * u.x;
        s.y = (x.y / (1.f + expf(-x.y))) * u.y;
        s.z = (x.z / (1.f + expf(-x.z))) * u.z;
        s.w = (x.w / (1.f + expf(-x.w))) * u.w;
        uint2 hi, lo; split4h(s, hi, lo);
        *(uint2*)(drow + i*4)      = hi;
        *(uint2*)(drow + FF + i*4) = lo;
    }
}

// ---------------- fused output: passthrough OR (residual + down-reduce(4)) * rw ----------------
__global__ void out_kernel(const float* __restrict__ hs, float* __restrict__ out) {
    int r = blockIdx.x;
    int g = d_selg[r];
    const float4* src = (const float4*)(hs + (size_t)r * D);
    float4* dst = (float4*)(out + (size_t)r * D);
    if (g < 0) {
        for (int i = threadIdx.x; i < D/4; i += 256) dst[i] = src[i];
    } else {
        float sc = d_rw[r];
        const float4* xs = (const float4*)(d_x + (size_t)g * D);
        const float4* p0 = (const float4*)(d_part + (size_t)g * D);
        const float4* p1 = (const float4*)(d_part + (size_t)RMAX * D + (size_t)g * D);
        const float4* p2 = (const float4*)(d_part + (size_t)2 * RMAX * D + (size_t)g * D);
        const float4* p3 = (const float4*)(d_part + (size_t)3 * RMAX * D + (size_t)g * D);
        for (int i = threadIdx.x; i < D/4; i += 256) {
            float4 v = xs[i], a = p0[i], b = p1[i], c = p2[i], d = p3[i];
            v.x = (v.x + a.x + b.x + c.x + d.x) * sc;
            v.y = (v.y + a.y + b.y + c.y + d.y) * sc;
            v.z = (v.z + a.z + b.z + c.z + d.z) * sc;
            v.w = (v.w + a.w + b.w + c.w + d.w) * sc;
            dst[i] = v;
        }
    }
}

// ---------------- launch ----------------
extern "C" void kernel_launch(void* const* d_in, const int* in_sizes, int n_in,
                              void* d_out, int out_size) {
    const float* hs    = (const float*)d_in[0];
    const float* rwv   = (const float*)d_in[1];
    const float* wq    = (const float*)d_in[2];
    const float* bq    = (const float*)d_in[3];
    const float* wk    = (const float*)d_in[4];
    const float* bk    = (const float*)d_in[5];
    const float* wv    = (const float*)d_in[6];
    const float* bv    = (const float*)d_in[7];
    const float* wo    = (const float*)d_in[8];
    const float* wgate = (const float*)d_in[9];
    const float* wup   = (const float*)d_in[10];
    const float* wdown = (const float*)d_in[11];
    const float* ln1w  = (const float*)d_in[12];
    const float* ln2w  = (const float*)d_in[13];
    float* out = (float*)d_out;

    float *px, *pq, *pk, *pv, *pg, *pu, *ppart;
    __half *pw2, *pa2;
    cudaGetSymbolAddress((void**)&px,    d_x);
    cudaGetSymbolAddress((void**)&pq,    d_q);
    cudaGetSymbolAddress((void**)&pk,    d_k);
    cudaGetSymbolAddress((void**)&pv,    d_v);
    cudaGetSymbolAddress((void**)&pg,    d_gg);
    cudaGetSymbolAddress((void**)&pu,    d_uu);
    cudaGetSymbolAddress((void**)&pw2,   d_w2);
    cudaGetSymbolAddress((void**)&pa2,   d_a2);
    cudaGetSymbolAddress((void**)&ppart, d_part);

    static int attr_done = 0;
    if (!attr_done) {
        cudaFuncSetAttribute(mma_gemm, cudaFuncAttributeMaxDynamicSharedMemorySize, SM_TOTAL);
        attr_done = 1;
    }

    router_kernel<<<BSROWS/8, 256>>>(hs, rwv);
    topk_kernel<<<B, 1024>>>();
    selmap_kernel<<<1, 1024>>>();
    gather_rms_a2_kernel<<<RMAX, 256>>>(hs, ln1w);

    // all weight conversions (hi-only fp16) in one launch
    {
        WAll wa;
        wa.s[0] = { wq,    pw2 + OFF_WQ, 2048*(D/8) };
        wa.s[1] = { wk,    pw2 + OFF_WK, 1024*(D/8) };
        wa.s[2] = { wv,    pw2 + OFF_WV, 1024*(D/8) };
        wa.s[3] = { wo,    pw2 + OFF_WO, 2048*(D/8) };
        wa.s[4] = { wgate, pw2 + OFF_WG, 8192*(D/8) };
        wa.s[5] = { wup,   pw2 + OFF_WU, 8192*(D/8) };
        wa.s[6] = { wdown, pw2 + OFF_WD, 2048*(FF/8) };
        convert_all_kernel<<<2368, 256>>>(wa);
    }

    // QKV GEMM
    {
        GArgs ga = {};
        ga.A2 = pa2; ga.K = D; ga.kSplit = 1; ga.nseg = 3;
        ga.s[0] = { pw2 + OFF_WQ, bq, pq, HQ*HD,  16 };
        ga.s[1] = { pw2 + OFF_WK, bk, pk, HKV*HD, 8  };
        ga.s[2] = { pw2 + OFF_WV, bv, pv, HKV*HD, 8  };
        mma_gemm<<<dim3(32, 4, 1), 128, SM_TOTAL>>>(ga);
    }
    rope_kernel<<<RMAX, 256>>>();
    attn_kernel<<<dim3(RMAX, HQ/8), dim3(32, 8)>>>();
    // O projection, split-K 2 -> partials
    {
        GArgs ga = {};
        ga.A2 = pa2; ga.K = D; ga.kSplit = 2; ga.nseg = 1;
        ga.s[0] = { pw2 + OFF_WO, nullptr, ppart, D, 16 };
        mma_gemm<<<dim3(16, 4, 2), 128, SM_TOTAL>>>(ga);
    }
    // fused: reduce(2) + residual + rmsnorm2 -> a2 (updates d_x)
    rms_reduce_a2_kernel<<<RMAX, 256>>>(ln2w);
    // gate + up merged
    {
        GArgs ga = {};
        ga.A2 = pa2; ga.K = D; ga.kSplit = 1; ga.nseg = 2;
        ga.s[0] = { pw2 + OFF_WG, nullptr, pg, FF, 64 };
        ga.s[1] = { pw2 + OFF_WU, nullptr, pu, FF, 64 };
        mma_gemm<<<dim3(128, 4, 1), 128, SM_TOTAL>>>(ga);
    }
    silu_a2_kernel<<<RMAX, 256>>>();
    // down, split-K 4 -> partials (reduced in out_kernel)
    {
        GArgs ga = {};
        ga.A2 = pa2; ga.K = FF; ga.kSplit = 4; ga.nseg = 1;
        ga.s[0] = { pw2 + OFF_WD, nullptr, ppart, D, 16 };
        mma_gemm<<<dim3(16, 4, 4), 128, SM_TOTAL>>>(ga);
    }

    // fused output: passthrough or (d_x + Σ parts) * rw
    out_kernel<<<BSROWS, 256>>>(hs, out);
}

// round 15
// speedup vs baseline: 2.1271x; 1.4150x over previous
#include <cuda_runtime.h>
#include <cuda_bf16.h>
#include <cuda_fp16.h>
#include <math.h>
#include <stdint.h>

// ---------------- problem constants ----------------
#define B   2
#define S   2048
#define D   2048
#define HQ  16
#define HKV 8
#define HD  128
#define FF  8192
#define KCAP 256
#define BSROWS (B*S)          // 4096
#define RMAX 512
#define EPSF 1e-6f

// ---------------- device scratch ----------------
__device__ float d_rw[BSROWS];
__device__ float d_thresh[B];
__device__ int   d_selidx[BSROWS];
__device__ int   d_selcnt[B];
__device__ int   d_off[B+1];
__device__ int   d_rows[1];
__device__ int   d_row_b[RMAX];
__device__ int   d_row_p[RMAX];
__device__ int   d_selg[BSROWS];
__device__ float d_x   [(size_t)RMAX*D];
__device__ float d_q   [(size_t)RMAX*HQ*HD];
__device__ float d_k   [(size_t)RMAX*HKV*HD];
__device__ float d_v   [(size_t)RMAX*HKV*HD];
__device__ float d_gg  [(size_t)RMAX*FF];
__device__ float d_uu  [(size_t)RMAX*FF];
__device__ float d_part[(size_t)4*RMAX*D];

// fp16 weights (K per row) and activations (K per row, hi only)
#define OFF_WQ 0
#define OFF_WK (OFF_WQ + (size_t)2048*D)
#define OFF_WV (OFF_WK + (size_t)1024*D)
#define OFF_WO (OFF_WV + (size_t)1024*D)
#define OFF_WG (OFF_WO + (size_t)2048*D)
#define OFF_WU (OFF_WG + (size_t)8192*D)
#define OFF_WD (OFF_WU + (size_t)8192*D)
#define W2_TOTAL (OFF_WD + (size_t)2048*FF)
__device__ __half d_w2[W2_TOTAL];
__device__ __half d_a2[(size_t)RMAX*FF];

// ---------------- helpers ----------------
__device__ __forceinline__ uint32_t smem_to_u32(const void* p) {
    uint32_t a;
    asm("{ .reg .u64 t; cvta.to.shared.u64 t, %1; cvt.u32.u64 %0, t; }" : "=r"(a) : "l"(p));
    return a;
}
__device__ __forceinline__ void cp_async16(uint32_t dst, const void* src, int sz) {
    asm volatile("cp.async.cg.shared.global [%0], [%1], 16, %2;"
                 :: "r"(dst), "l"(src), "r"(sz) : "memory");
}
__device__ __forceinline__ void cp_commit() { asm volatile("cp.async.commit_group;" ::: "memory"); }
__device__ __forceinline__ void cp_wait1()  { asm volatile("cp.async.wait_group 1;" ::: "memory"); }
__device__ __forceinline__ void ldsm4(uint32_t& r0, uint32_t& r1, uint32_t& r2, uint32_t& r3, uint32_t a) {
    asm volatile("ldmatrix.sync.aligned.m8n8.x4.shared.b16 {%0,%1,%2,%3}, [%4];"
                 : "=r"(r0), "=r"(r1), "=r"(r2), "=r"(r3) : "r"(a));
}
__device__ __forceinline__ void mma_f16(float* c, const uint32_t* a, uint32_t b0, uint32_t b1) {
    asm volatile("mma.sync.aligned.m16n8k16.row.col.f32.f16.f16.f32 "
                 "{%0,%1,%2,%3}, {%4,%5,%6,%7}, {%8,%9}, {%0,%1,%2,%3};"
                 : "+f"(c[0]), "+f"(c[1]), "+f"(c[2]), "+f"(c[3])
                 : "r"(a[0]), "r"(a[1]), "r"(a[2]), "r"(a[3]), "r"(b0), "r"(b1));
}
// convert fp32x4 -> fp16x4 (packed as uint2)
__device__ __forceinline__ uint2 cvt4h(float4 v) {
    __half2 h01 = __floats2half2_rn(v.x, v.y);
    __half2 h23 = __floats2half2_rn(v.z, v.w);
    return make_uint2(*(uint32_t*)&h01, *(uint32_t*)&h23);
}

// ---------------- merged weight conversion: W f32 -> fp16 ----------------
struct WSeg { const float* src; __half* dst; int total; };
struct WAll { WSeg s[7]; };

__global__ void convert_all_kernel(WAll wa) {
    #pragma unroll 1
    for (int sgi = 0; sgi < 7; sgi++) {
        const float* __restrict__ src = wa.s[sgi].src;
        __half* __restrict__ dst = wa.s[sgi].dst;
        int total = wa.s[sgi].total;       // N*K/8
        for (int idx = blockIdx.x * 256 + threadIdx.x; idx < total; idx += gridDim.x * 256) {
            size_t c8 = (size_t)idx << 3;
            const float* sp = src + c8;
            float4 v0 = *(const float4*)(sp);
            float4 v1 = *(const float4*)(sp + 4);
            uint2 a = cvt4h(v0), b = cvt4h(v1);
            *(uint4*)(dst + c8) = make_uint4(a.x, a.y, b.x, b.y);
        }
    }
}

// ---------------- tensor-core GEMM (pure fp16, fp32 accum) ----------------
// C[M,N] = A[M,K] @ W[N,K]^T (+bias). CTA tile 128x128, 128 threads
// (2x2 warps, 64x64 warp tile), BK=64, 3-stage cp.async.
struct Seg { const __half* W2; const float* bias; float* C; int N; int ntiles; };
struct GArgs { const __half* A2; int K; int kSplit; int nseg; Seg s[3]; };

#define STAGES 3
#define STAGE_BYTES 32768   // A 16KB + W 16KB (128 rows x 128 bytes each)
#define SM_TOTAL (STAGES*STAGE_BYTES)

__global__ void __launch_bounds__(128, 2) mma_gemm(GArgs ga) {
    extern __shared__ char smem[];
    uint32_t sb = smem_to_u32(smem);
    int tid = threadIdx.x;
    int rows = d_rows[0]; if (rows > RMAX) rows = RMAX;
    int m0 = blockIdx.y * 128;
    int Kp = ga.K;

    Seg sg = ga.s[0];
    int nt = blockIdx.x;
    if (ga.nseg > 1 && nt >= ga.s[0].ntiles) {
        nt -= ga.s[0].ntiles; sg = ga.s[1];
        if (ga.nseg > 2 && nt >= ga.s[1].ntiles) { nt -= ga.s[1].ntiles; sg = ga.s[2]; }
    }
    int n0g = nt * 128;
    int kLen = Kp / ga.kSplit;
    int kOff = blockIdx.z * kLen;
    int iters = kLen / 64;

    const __half* Abase = ga.A2;
    const __half* Wbase = sg.W2 + (size_t)n0g * Kp;

    // loader: per stage A = 1024 16B-chunks (8/thread), W = 1024 (8/thread)
    int lrow[8], lch[8]; uint32_t lsw[8];
    #pragma unroll
    for (int q = 0; q < 8; q++) {
        int j = tid + q * 128;
        lrow[q] = j >> 3; lch[q] = j & 7;
        lsw[q] = lrow[q] * 128 + ((lch[q] ^ (lrow[q] & 7)) << 4);
    }

    #define LOAD_STAGE(stage, kElem) do { \
        uint32_t sA = sb + (stage) * STAGE_BYTES; \
        uint32_t sW = sA + 16384; \
        _Pragma("unroll") \
        for (int q = 0; q < 8; q++) { \
            int gm = m0 + lrow[q]; \
            cp_async16(sA + lsw[q], Abase + (size_t)gm * Kp + (kElem) + lch[q]*8, gm < rows ? 16 : 0); \
            cp_async16(sW + lsw[q], Wbase + (size_t)lrow[q] * Kp + (kElem) + lch[q]*8, 16); \
        } \
    } while (0)

    LOAD_STAGE(0, kOff); cp_commit();
    LOAD_STAGE(1, kOff + 64); cp_commit();

    int lane = tid & 31, wid = tid >> 5;
    int wm = wid >> 1, wn = wid & 1;       // 2x2 warp grid, 64x64 tiles
    float acc[4][8][4];
    #pragma unroll
    for (int a = 0; a < 4; a++)
        #pragma unroll
        for (int b = 0; b < 8; b++)
            #pragma unroll
            for (int c = 0; c < 4; c++) acc[a][b][c] = 0.f;

    int arow_[4];
    #pragma unroll
    for (int mi = 0; mi < 4; mi++) arow_[mi] = wm * 64 + mi * 16 + (lane & 15);
    int ach_ = lane >> 4;
    int brow_[4];
    #pragma unroll
    for (int p = 0; p < 4; p++) brow_[p] = wn * 64 + p * 16 + (lane & 7) + ((lane >> 4) << 3);
    int bch_ = (lane >> 3) & 1;

    for (int i = 0; i < iters; i++) {
        cp_wait1();
        __syncthreads();
        int nf = i + STAGES - 1;
        if (nf < iters) LOAD_STAGE(nf % STAGES, kOff + nf * 64);
        cp_commit();

        uint32_t sA = sb + (i % STAGES) * STAGE_BYTES;
        uint32_t sW = sA + 16384;
        #pragma unroll
        for (int s2 = 0; s2 < 4; s2++) {
            uint32_t af[4][4];
            #pragma unroll
            for (int mi = 0; mi < 4; mi++) {
                int row = arow_[mi];
                int ch = 2 * s2 + ach_;
                uint32_t ad = sA + row * 128 + ((ch ^ (row & 7)) << 4);
                ldsm4(af[mi][0], af[mi][1], af[mi][2], af[mi][3], ad);
            }
            uint32_t b0[8], b1[8];
            #pragma unroll
            for (int p = 0; p < 4; p++) {
                int row = brow_[p];
                int ch = 2 * s2 + bch_;
                uint32_t bd = sW + row * 128 + ((ch ^ (row & 7)) << 4);
                uint32_t r0, r1, r2, r3;
                ldsm4(r0, r1, r2, r3, bd);
                b0[2*p] = r0; b1[2*p] = r1; b0[2*p+1] = r2; b1[2*p+1] = r3;
            }
            #pragma unroll
            for (int mi = 0; mi < 4; mi++)
                #pragma unroll
                for (int ni = 0; ni < 8; ni++)
                    mma_f16(acc[mi][ni], af[mi], b0[ni], b1[ni]);
        }
        __syncthreads();
    }

    float* Cp = sg.C + (ga.kSplit > 1 ? (size_t)blockIdx.z * RMAX * sg.N : 0);
    int rr = lane >> 2;
    int cc = (lane & 3) * 2;
    #pragma unroll
    for (int mi = 0; mi < 4; mi++) {
        int m1 = m0 + wm * 64 + mi * 16 + rr;
        #pragma unroll
        for (int ni = 0; ni < 8; ni++) {
            int n1 = n0g + wn * 64 + ni * 8 + cc;
            float bx = 0.f, by = 0.f;
            if (sg.bias) { bx = sg.bias[n1]; by = sg.bias[n1 + 1]; }
            if (m1 < rows)
                *(float2*)(Cp + (size_t)m1 * sg.N + n1) =
                    make_float2(acc[mi][ni][0] + bx, acc[mi][ni][1] + by);
            if (m1 + 8 < rows)
                *(float2*)(Cp + (size_t)(m1 + 8) * sg.N + n1) =
                    make_float2(acc[mi][ni][2] + bx, acc[mi][ni][3] + by);
        }
    }
    #undef LOAD_STAGE
}

// ---------------- router / topk / select+map ----------------
__global__ void router_kernel(const float* __restrict__ hs, const float* __restrict__ rwv) {
    int row  = blockIdx.x * 8 + (threadIdx.x >> 5);
    int lane = threadIdx.x & 31;
    if (row >= BSROWS) return;
    const float* x = hs + (size_t)row * D;
    float s = 0.f;
    for (int i = lane; i < D; i += 32) s += x[i] * rwv[i];
    #pragma unroll
    for (int o = 16; o; o >>= 1) s += __shfl_xor_sync(0xffffffffu, s, o);
    if (lane == 0) d_rw[row] = s;
}

__global__ void topk_kernel() {
    __shared__ float s[S];
    int b = blockIdx.x;
    int t = threadIdx.x;
    s[t] = d_rw[b*S + t]; s[t + 1024] = d_rw[b*S + t + 1024];
    for (int k = 2; k <= S; k <<= 1)
        for (int j = k >> 1; j > 0; j >>= 1) {
            __syncthreads();
            for (int i = t; i < S; i += 1024) {
                int ixj = i ^ j;
                if (ixj > i) {
                    bool up = ((i & k) == 0);
                    float a = s[i], c = s[ixj];
                    if ((a > c) == up) { s[i] = c; s[ixj] = a; }
                }
            }
        }
    __syncthreads();
    if (t == 0) d_thresh[b] = s[S - KCAP];
}

__global__ void selmap_kernel() {
    int t = threadIdx.x;                      // 1024 threads
    for (int i = t; i < BSROWS; i += 1024) d_selg[i] = -1;
    int wid = t >> 5, lane = t & 31;
    if (wid < B) {
        int b = wid;
        float th = d_thresh[b];
        int total = 0;
        for (int c = 0; c < S/32; c++) {
            int idx = c*32 + lane;
            bool f = d_rw[b*S + idx] >= th;
            unsigned m = __ballot_sync(0xffffffffu, f);
            int pre = __popc(m & ((1u << lane) - 1u));
            if (f) d_selidx[b*S + total + pre] = idx;
            total += __popc(m);
        }
        if (lane == 0) d_selcnt[b] = total;
    }
    __syncthreads();
    int c0 = d_selcnt[0], c1 = d_selcnt[1];
    int rows = c0 + c1; if (rows > RMAX) rows = RMAX;
    if (t == 0) { d_off[0]=0; d_off[1]=c0; d_off[2]=c0+c1; d_rows[0]=rows; }
    for (int i = t; i < c0; i += 1024) if (i < RMAX) {
        int p = d_selidx[i];
        d_row_b[i] = 0; d_row_p[i] = p; d_selg[p] = i;
    }
    for (int i = t; i < c1; i += 1024) if (c0 + i < RMAX) {
        int p = d_selidx[S + i];
        d_row_b[c0+i] = 1; d_row_p[c0+i] = p; d_selg[S + p] = c0 + i;
    }
}

// ---------------- gather + rmsnorm -> a2 (and d_x) fused ----------------
__global__ void gather_rms_a2_kernel(const float* __restrict__ hs, const float* __restrict__ w) {
    int g = blockIdx.x;
    if (g >= d_rows[0]) return;
    int b = d_row_b[g], p = d_row_p[g];
    const float4* src = (const float4*)(hs + ((size_t)b*S + p) * D);
    float4* dx = (float4*)(d_x + (size_t)g * D);
    float ss = 0.f;
    for (int i = threadIdx.x; i < D/4; i += 256) {
        float4 v = src[i]; dx[i] = v;
        ss += v.x*v.x + v.y*v.y + v.z*v.z + v.w*v.w;
    }
    __shared__ float red[8];
    int lane = threadIdx.x & 31, wid = threadIdx.x >> 5;
    #pragma unroll
    for (int o = 16; o; o >>= 1) ss += __shfl_xor_sync(0xffffffffu, ss, o);
    if (lane == 0) red[wid] = ss;
    __syncthreads();
    if (threadIdx.x == 0) { float v=0.f; for (int i=0;i<8;i++) v+=red[i]; red[0]=v; }
    __syncthreads();
    float inv = rsqrtf(red[0] / (float)D + EPSF);
    __half* drow = d_a2 + (size_t)g * D;
    const float4* wv4 = (const float4*)w;
    for (int i = threadIdx.x; i < D/4; i += 256) {
        float4 v = dx[i], ww = wv4[i];
        float4 hv = make_float4(v.x*inv*ww.x, v.y*inv*ww.y, v.z*inv*ww.z, v.w*inv*ww.w);
        *(uint2*)(drow + i*4) = cvt4h(hv);
    }
}

// ---------------- O-reduce(2) + residual + rmsnorm -> a2, updates d_x ----------------
__global__ void rms_reduce_a2_kernel(const float* __restrict__ w) {
    int g = blockIdx.x;
    if (g >= d_rows[0]) return;
    float4* dx = (float4*)(d_x + (size_t)g * D);
    const float4* p0 = (const float4*)(d_part + (size_t)g * D);
    const float4* p1 = (const float4*)(d_part + (size_t)RMAX * D + (size_t)g * D);
    float ss = 0.f;
    for (int i = threadIdx.x; i < D/4; i += 256) {
        float4 v = dx[i], a = p0[i], b = p1[i];
        v.x += a.x + b.x; v.y += a.y + b.y; v.z += a.z + b.z; v.w += a.w + b.w;
        dx[i] = v;
        ss += v.x*v.x + v.y*v.y + v.z*v.z + v.w*v.w;
    }
    __shared__ float red[8];
    int lane = threadIdx.x & 31, wid = threadIdx.x >> 5;
    #pragma unroll
    for (int o = 16; o; o >>= 1) ss += __shfl_xor_sync(0xffffffffu, ss, o);
    if (lane == 0) red[wid] = ss;
    __syncthreads();
    if (threadIdx.x == 0) { float v=0.f; for (int i=0;i<8;i++) v+=red[i]; red[0]=v; }
    __syncthreads();
    float inv = rsqrtf(red[0] / (float)D + EPSF);
    __half* drow = d_a2 + (size_t)g * D;
    const float4* wv4 = (const float4*)w;
    for (int i = threadIdx.x; i < D/4; i += 256) {
        float4 v = dx[i], ww = wv4[i];
        float4 hv = make_float4(v.x*inv*ww.x, v.y*inv*ww.y, v.z*inv*ww.z, v.w*inv*ww.w);
        *(uint2*)(drow + i*4) = cvt4h(hv);
    }
}

// ---------------- RoPE ----------------
__global__ void rope_kernel() {
    int g = blockIdx.x;
    if (g >= d_rows[0]) return;
    float fp = (float)d_row_p[g];
    const float L2_10000 = 13.287712379549449f;
    for (int idx = threadIdx.x; idx < (HQ + HKV) * 64; idx += 256) {
        int head = idx >> 6;
        int i = idx & 63;
        float inv = exp2f(-(float)i * (L2_10000 / 64.0f));
        float fr = fp * inv;
        float c = cosf(fr), s = sinf(fr);
        float* ptr;
        if (head < HQ) ptr = d_q + (size_t)g*(HQ*HD) + head*HD;
        else           ptr = d_k + (size_t)g*(HKV*HD) + (head-HQ)*HD;
        float x1 = ptr[i], x2 = ptr[i+64];
        ptr[i]    = x1*c - x2*s;
        ptr[i+64] = x2*c + x1*s;
    }
}

// ---------------- attention -> a2 directly ----------------
__global__ void attn_kernel() {
    int g = blockIdx.x;
    if (g >= d_rows[0]) return;
    int h = threadIdx.y + blockIdx.y * 8;
    int b = d_row_b[g];
    int off = d_off[b];
    int r = g - off;
    int p = d_row_p[g];
    int lane = threadIdx.x;
    int kvh = h >> 1;

    float4 qv = *(const float4*)(d_q + (size_t)g*(HQ*HD) + h*HD + lane*4);
    const float scale = 0.08838834764831843f;

    float m = -INFINITY, l = 0.f;
    float4 acc = make_float4(0.f, 0.f, 0.f, 0.f);

    for (int j = 0; j <= r; j++) {
        const float* kp = d_k + (size_t)(off + j)*(HKV*HD) + kvh*HD;
        float4 kv = *(const float4*)(kp + lane*4);
        float sdot = qv.x*kv.x + qv.y*kv.y + qv.z*kv.z + qv.w*kv.w;
        #pragma unroll
        for (int o = 16; o; o >>= 1) sdot += __shfl_xor_sync(0xffffffffu, sdot, o);
        float sc = sdot * scale;
        float mn = fmaxf(m, sc);
        float eo = expf(m - mn);
        float ec = expf(sc - mn);
        const float* vp = d_v + (size_t)(off + j)*(HKV*HD) + kvh*HD;
        float4 vv = *(const float4*)(vp + lane*4);
        l = l*eo + ec;
        acc.x = acc.x*eo + ec*vv.x;
        acc.y = acc.y*eo + ec*vv.y;
        acc.z = acc.z*eo + ec*vv.z;
        acc.w = acc.w*eo + ec*vv.w;
        m = mn;
    }
    int zc = p - r;
    if (zc > 0) {
        float mn = fmaxf(m, 0.f);
        float eo = expf(m - mn);
        l = l*eo + (float)zc * expf(-mn);
        acc.x *= eo; acc.y *= eo; acc.z *= eo; acc.w *= eo;
    }
    float invl = 1.f / l;
    float4 o4 = make_float4(acc.x*invl, acc.y*invl, acc.z*invl, acc.w*invl);
    __half* drow = d_a2 + (size_t)g * D + h * HD + lane * 4;
    *(uint2*)(drow) = cvt4h(o4);
}

// ---------------- silu(g)*u -> a2 (K=FF) ----------------
__global__ void silu_a2_kernel() {
    int g = blockIdx.x;
    if (g >= d_rows[0]) return;
    const float4* gr = (const float4*)(d_gg + (size_t)g * FF);
    const float4* ur = (const float4*)(d_uu + (size_t)g * FF);
    __half* drow = d_a2 + (size_t)g * FF;
    for (int i = threadIdx.x; i < FF/4; i += 256) {
        float4 x = gr[i], u = ur[i];
        float4 s;
        s.x = (x.x / (1.f + expf(-x.x))) * u.x;
        s.y = (x.y / (1.f + expf(-x.y))) * u.y;
        s.z = (x.z / (1.f + expf(-x.z))) * u.z;
        s.w = (x.w / (1.f + expf(-x.w))) * u.w;
        *(uint2*)(drow + i*4) = cvt4h(s);
    }
}

// ---------------- fused output: passthrough OR (residual + down-reduce(4)) * rw ----------------
__global__ void out_kernel(const float* __restrict__ hs, float* __restrict__ out) {
    int r = blockIdx.x;
    int g = d_selg[r];
    const float4* src = (const float4*)(hs + (size_t)r * D);
    float4* dst = (float4*)(out + (size_t)r * D);
    if (g < 0) {
        for (int i = threadIdx.x; i < D/4; i += 256) dst[i] = src[i];
    } else {
        float sc = d_rw[r];
        const float4* xs = (const float4*)(d_x + (size_t)g * D);
        const float4* p0 = (const float4*)(d_part + (size_t)g * D);
        const float4* p1 = (const float4*)(d_part + (size_t)RMAX * D + (size_t)g * D);
        const float4* p2 = (const float4*)(d_part + (size_t)2 * RMAX * D + (size_t)g * D);
        const float4* p3 = (const float4*)(d_part + (size_t)3 * RMAX * D + (size_t)g * D);
        for (int i = threadIdx.x; i < D/4; i += 256) {
            float4 v = xs[i], a = p0[i], b = p1[i], c = p2[i], d = p3[i];
            v.x = (v.x + a.x + b.x + c.x + d.x) * sc;
            v.y = (v.y + a.y + b.y + c.y + d.y) * sc;
            v.z = (v.z + a.z + b.z + c.z + d.z) * sc;
            v.w = (v.w + a.w + b.w + c.w + d.w) * sc;
            dst[i] = v;
        }
    }
}

// ---------------- launch ----------------
extern "C" void kernel_launch(void* const* d_in, const int* in_sizes, int n_in,
                              void* d_out, int out_size) {
    const float* hs    = (const float*)d_in[0];
    const float* rwv   = (const float*)d_in[1];
    const float* wq    = (const float*)d_in[2];
    const float* bq    = (const float*)d_in[3];
    const float* wk    = (const float*)d_in[4];
    const float* bk    = (const float*)d_in[5];
    const float* wv    = (const float*)d_in[6];
    const float* bv    = (const float*)d_in[7];
    const float* wo    = (const float*)d_in[8];
    const float* wgate = (const float*)d_in[9];
    const float* wup   = (const float*)d_in[10];
    const float* wdown = (const float*)d_in[11];
    const float* ln1w  = (const float*)d_in[12];
    const float* ln2w  = (const float*)d_in[13];
    float* out = (float*)d_out;

    float *px, *pq, *pk, *pv, *pg, *pu, *ppart;
    __half *pw2, *pa2;
    cudaGetSymbolAddress((void**)&px,    d_x);
    cudaGetSymbolAddress((void**)&pq,    d_q);
    cudaGetSymbolAddress((void**)&pk,    d_k);
    cudaGetSymbolAddress((void**)&pv,    d_v);
    cudaGetSymbolAddress((void**)&pg,    d_gg);
    cudaGetSymbolAddress((void**)&pu,    d_uu);
    cudaGetSymbolAddress((void**)&pw2,   d_w2);
    cudaGetSymbolAddress((void**)&pa2,   d_a2);
    cudaGetSymbolAddress((void**)&ppart, d_part);

    static int attr_done = 0;
    if (!attr_done) {
        cudaFuncSetAttribute(mma_gemm, cudaFuncAttributeMaxDynamicSharedMemorySize, SM_TOTAL);
        attr_done = 1;
    }

    router_kernel<<<BSROWS/8, 256>>>(hs, rwv);
    topk_kernel<<<B, 1024>>>();
    selmap_kernel<<<1, 1024>>>();
    gather_rms_a2_kernel<<<RMAX, 256>>>(hs, ln1w);

    // all weight conversions (fp16) in one launch
    {
        WAll wa;
        wa.s[0] = { wq,    pw2 + OFF_WQ, 2048*(D/8) };
        wa.s[1] = { wk,    pw2 + OFF_WK, 1024*(D/8) };
        wa.s[2] = { wv,    pw2 + OFF_WV, 1024*(D/8) };
        wa.s[3] = { wo,    pw2 + OFF_WO, 2048*(D/8) };
        wa.s[4] = { wgate, pw2 + OFF_WG, 8192*(D/8) };
        wa.s[5] = { wup,   pw2 + OFF_WU, 8192*(D/8) };
        wa.s[6] = { wdown, pw2 + OFF_WD, 2048*(FF/8) };
        convert_all_kernel<<<2368, 256>>>(wa);
    }

    // QKV GEMM
    {
        GArgs ga = {};
        ga.A2 = pa2; ga.K = D; ga.kSplit = 1; ga.nseg = 3;
        ga.s[0] = { pw2 + OFF_WQ, bq, pq, HQ*HD,  16 };
        ga.s[1] = { pw2 + OFF_WK, bk, pk, HKV*HD, 8  };
        ga.s[2] = { pw2 + OFF_WV, bv, pv, HKV*HD, 8  };
        mma_gemm<<<dim3(32, 4, 1), 128, SM_TOTAL>>>(ga);
    }
    rope_kernel<<<RMAX, 256>>>();
    attn_kernel<<<dim3(RMAX, HQ/8), dim3(32, 8)>>>();
    // O projection, split-K 2 -> partials
    {
        GArgs ga = {};
        ga.A2 = pa2; ga.K = D; ga.kSplit = 2; ga.nseg = 1;
        ga.s[0] = { pw2 + OFF_WO, nullptr, ppart, D, 16 };
        mma_gemm<<<dim3(16, 4, 2), 128, SM_TOTAL>>>(ga);
    }
    // fused: reduce(2) + residual + rmsnorm2 -> a2 (updates d_x)
    rms_reduce_a2_kernel<<<RMAX, 256>>>(ln2w);
    // gate + up merged
    {
        GArgs ga = {};
        ga.A2 = pa2; ga.K = D; ga.kSplit = 1; ga.nseg = 2;
        ga.s[0] = { pw2 + OFF_WG, nullptr, pg, FF, 64 };
        ga.s[1] = { pw2 + OFF_WU, nullptr, pu, FF, 64 };
        mma_gemm<<<dim3(128, 4, 1), 128, SM_TOTAL>>>(ga);
    }
    silu_a2_kernel<<<RMAX, 256>>>();
    // down, split-K 4 -> partials (reduced in out_kernel)
    {
        GArgs ga = {};
        ga.A2 = pa2; ga.K = FF; ga.kSplit = 4; ga.nseg = 1;
        ga.s[0] = { pw2 + OFF_WD, nullptr, ppart, D, 16 };
        mma_gemm<<<dim3(16, 4, 4), 128, SM_TOTAL>>>(ga);
    }

    // fused output: passthrough or (d_x + Σ parts) * rw
    out_kernel<<<BSROWS, 256>>>(hs, out);
}